// round 8
// baseline (speedup 1.0000x reference)
#include <cuda_runtime.h>
#include <cuda_bf16.h>
#include <cstdint>
#include <math.h>

#define B_   2
#define T_   2048
#define C_   2048
#define H_   16
#define D_   128
#define HALF_ 64
#define M_   (B_*T_)       // 4096
#define N1_  (3*C_)        // 6144
#define RS_  (3*C_)
#define BH_  (B_*H_)       // 32

// ---------------- scratch (device globals) ----------------
__device__ float g_qkv[(size_t)M_ * N1_];              // [B*T, 3*C] fp32 (GEMM1 out)
__device__ float g_sin[T_ * HALF_];
__device__ float g_cos[T_ * HALF_];
__device__ __nv_bfloat16 g_qh[(size_t)BH_ * T_ * D_];  // roped+scaled Q hi/lo, head-major
__device__ __nv_bfloat16 g_ql[(size_t)BH_ * T_ * D_];
__device__ __nv_bfloat16 g_kh[(size_t)BH_ * T_ * D_];
__device__ __nv_bfloat16 g_kl[(size_t)BH_ * T_ * D_];
__device__ __nv_bfloat16 g_vh[(size_t)BH_ * T_ * D_];
__device__ __nv_bfloat16 g_vl[(size_t)BH_ * T_ * D_];
__device__ __nv_bfloat16 g_xh[(size_t)M_ * C_];        // x split [M][K]
__device__ __nv_bfloat16 g_xl[(size_t)M_ * C_];
__device__ __nv_bfloat16 g_w1h[(size_t)C_ * N1_];      // Wqkv split [K][N]
__device__ __nv_bfloat16 g_w1l[(size_t)C_ * N1_];
__device__ __nv_bfloat16 g_w2h[(size_t)C_ * C_];       // Wout split [K][N]
__device__ __nv_bfloat16 g_w2l[(size_t)C_ * C_];
__device__ __nv_bfloat16 g_oh[(size_t)M_ * C_];        // attention out split (flat B,H,T,D)
__device__ __nv_bfloat16 g_ol[(size_t)M_ * C_];

// ---------------- fast exp (FFMA-pipe) --------------
__device__ __forceinline__ float fast_exp(float x) {
    x = fmaxf(x, -87.0f);
    float t = x * 1.4426950408889634f;
    int   i = __float2int_rn(t);
    float f = t - (float)i;
    float p =          1.3333558146428443e-3f;
    p = fmaf(p, f, 9.6181291780723730e-3f);
    p = fmaf(p, f, 5.5504108664821580e-2f);
    p = fmaf(p, f, 2.4022650695910072e-1f);
    p = fmaf(p, f, 6.9314718055994531e-1f);
    p = fmaf(p, f, 1.0f);
    return __int_as_float((i + 127) << 23) * p;
}

// ---------------- MMA / LDSM / cp.async primitives ----------------
#define LDSM_X4(R0,R1,R2,R3,ADDR) \
    asm volatile("ldmatrix.sync.aligned.m8n8.x4.shared.b16 {%0,%1,%2,%3}, [%4];" \
                 : "=r"(R0), "=r"(R1), "=r"(R2), "=r"(R3) : "r"(ADDR))
#define LDSM_X4_T(R0,R1,R2,R3,ADDR) \
    asm volatile("ldmatrix.sync.aligned.m8n8.x4.trans.shared.b16 {%0,%1,%2,%3}, [%4];" \
                 : "=r"(R0), "=r"(R1), "=r"(R2), "=r"(R3) : "r"(ADDR))
#define CP16(DST, SRC) \
    asm volatile("cp.async.cg.shared.global [%0], [%1], 16;" :: "r"(DST), "l"(SRC))
#define CP_COMMIT()  asm volatile("cp.async.commit_group;" ::: "memory")
#define CP_WAIT0()   asm volatile("cp.async.wait_group 0;" ::: "memory")
#define CP_WAIT1()   asm volatile("cp.async.wait_group 1;" ::: "memory")

__device__ __forceinline__ void mma16816(float* d, const unsigned* a, const unsigned* b) {
    asm volatile(
        "mma.sync.aligned.m16n8k16.row.col.f32.bf16.bf16.f32 "
        "{%0,%1,%2,%3}, {%4,%5,%6,%7}, {%8,%9}, {%0,%1,%2,%3};"
        : "+f"(d[0]), "+f"(d[1]), "+f"(d[2]), "+f"(d[3])
        : "r"(a[0]), "r"(a[1]), "r"(a[2]), "r"(a[3]), "r"(b[0]), "r"(b[1]));
}

__device__ __forceinline__ void split2(float x, float y, unsigned& hi, unsigned& lo) {
    __nv_bfloat162 h2 = __floats2bfloat162_rn(x, y);
    float hx = __bfloat162float(h2.x);
    float hy = __bfloat162float(h2.y);
    __nv_bfloat162 l2 = __floats2bfloat162_rn(x - hx, y - hy);
    hi = *reinterpret_cast<unsigned*>(&h2);
    lo = *reinterpret_cast<unsigned*>(&l2);
}

// ---------------- pre-pass: elementwise fp32 -> bf16 hi/lo split (vectorized) ----
__global__ void split_kernel(const float* __restrict__ src,
                             __nv_bfloat16* __restrict__ th,
                             __nv_bfloat16* __restrict__ tl)
{
    size_t i = ((size_t)blockIdx.x * blockDim.x + threadIdx.x) * 4;
    float4 v = *(const float4*)(src + i);
    unsigned h0, l0, h1, l1;
    split2(v.x, v.y, h0, l0);
    split2(v.z, v.w, h1, l1);
    *(uint2*)(th + i) = make_uint2(h0, h1);
    *(uint2*)(tl + i) = make_uint2(l0, l1);
}

// =================================================================================
//  bf16x3 split-precision tensor-core GEMM, cp.async 3-stage pipeline, BK=32,
//  2 CTAs/SM, PERSISTENT (grid-stride over 128x128 tiles to kill wave quantization).
// =================================================================================
#define SGBH  16384
#define SGBL  24576
#define STAGE_ 32768
#define NSTAGE 3
#define GSM_TOTAL (NSTAGE * STAGE_)   // 98304
#define GEMM_GRID 296                 // 2 CTAs/SM x 148 SMs

__global__ void __launch_bounds__(256, 2) mma_gemm(const __nv_bfloat16* __restrict__ Ah,
                                                   const __nv_bfloat16* __restrict__ Al,
                                                   const __nv_bfloat16* __restrict__ Bh,
                                                   const __nv_bfloat16* __restrict__ Bl,
                                                   float* __restrict__ C,
                                                   int M, int N, int K)
{
    extern __shared__ char smem[];
    const uint32_t smem_u32 = (uint32_t)__cvta_generic_to_shared(smem);

    const int tid  = threadIdx.x;
    const int lane = tid & 31;
    const int wid  = tid >> 5;
    const int warp_m = wid & 1;
    const int warp_n = wid >> 1;
    const int quad = lane >> 3;
    const int rq   = lane & 7;

    // ---- tile-independent staging geometry ----
    uint32_t swA[4], swB[4];
    int raA[4], caA[4];          // A row/chunk per slot
    int rbB[4], cbB[4], hlB[4];  // B row/chunk/hilo per slot
#pragma unroll
    for (int i = 0; i < 4; i++) {
        int ia = i * 256 + tid;
        raA[i] = ia >> 3; caA[i] = ia & 7;
        swA[i] = raA[i] * 128 + ((caA[i] ^ (raA[i] & 7)) << 4);
        int hilo = ia >> 9;
        int rem  = ia & 511;
        rbB[i] = rem >> 4; cbB[i] = rem & 15; hlB[i] = hilo;
        swB[i] = (hilo ? SGBL : SGBH) + rbB[i] * 256 +
                 (((cbB[i] & 8) | ((cbB[i] & 7) ^ (rbB[i] & 7))) << 4);
    }

    // ---- ldmatrix lane addressing (tile-independent) ----
    const int aRowL = warp_m * 64 + (quad & 1) * 8 + rq;
    const int kHalf = quad >> 1;
    const int arow7 = aRowL & 7;
    const int arowByte = aRowL * 128;

    const int kL = (quad & 1) * 8 + rq;
    int nbswp[2];
#pragma unroll
    for (int p = 0; p < 2; p++) {
        int nb = warp_n * 4 + (quad >> 1) + p * 2;
        nbswp[p] = (nb & 8) | ((nb & 7) ^ (kL & 7));
    }
    const int bByteBase = kL * 256;

    const int MB = M >> 7;               // tiles along M
    const int ntiles = MB * (N >> 7);
    const int KT = K >> 5;               // 64 stages of 32

    for (int tile = blockIdx.x; tile < ntiles; tile += gridDim.x) {
        const int bm = (tile % MB) * 128;    // bm fastest: concurrent CTAs share B panels
        const int bn = (tile / MB) * 128;

        const __nv_bfloat16* pA[4];
        const __nv_bfloat16* pB[4];
#pragma unroll
        for (int i = 0; i < 4; i++) {
            pA[i] = (caA[i] < 4 ? Ah : Al) + (size_t)(bm + raA[i]) * K + (caA[i] & 3) * 8;
            pB[i] = (hlB[i] ? Bl : Bh) + (size_t)rbB[i] * N + bn + cbB[i] * 8;
        }

        float acc[4][4][4];
#pragma unroll
        for (int mt = 0; mt < 4; mt++)
#pragma unroll
            for (int nt = 0; nt < 4; nt++)
#pragma unroll
                for (int c = 0; c < 4; c++) acc[mt][nt][c] = 0.f;

#define G_ISSUE(k0, buf) do { \
    const uint32_t b_ = smem_u32 + (buf) * STAGE_; \
    _Pragma("unroll") for (int i = 0; i < 4; i++) { \
        CP16(b_ + swA[i], pA[i] + (k0)); \
        CP16(b_ + swB[i], pB[i] + (size_t)(k0) * N); } \
    CP_COMMIT(); } while (0)

        G_ISSUE(0, 0);
        G_ISSUE(32, 1);

        for (int kt = 0; kt < KT; kt++) {
            if (kt + 1 < KT) { CP_WAIT1(); } else { CP_WAIT0(); }
            __syncthreads();
            if (kt + 2 < KT) G_ISSUE((kt + 2) * 32, (kt + 2) % NSTAGE);

            const uint32_t sbase = smem_u32 + (kt % NSTAGE) * STAGE_;
#pragma unroll
            for (int kk = 0; kk < 2; kk++) {
                unsigned ah[4][4], al[4][4], bh[2][4], bl[2][4];
                const int chi = 2 * kk + kHalf;
                const int asw_h = ((chi)     ^ arow7) << 4;
                const int asw_l = ((chi + 4) ^ arow7) << 4;
#pragma unroll
                for (int mt = 0; mt < 4; mt++) {
                    uint32_t ad = sbase + arowByte + mt * 2048;
                    LDSM_X4(ah[mt][0], ah[mt][1], ah[mt][2], ah[mt][3], ad + asw_h);
                    LDSM_X4(al[mt][0], al[mt][1], al[mt][2], al[mt][3], ad + asw_l);
                }
#pragma unroll
                for (int p = 0; p < 2; p++) {
                    uint32_t bd = sbase + kk * 4096 + bByteBase + nbswp[p] * 16;
                    LDSM_X4_T(bh[p][0], bh[p][1], bh[p][2], bh[p][3], bd + SGBH);
                    LDSM_X4_T(bl[p][0], bl[p][1], bl[p][2], bl[p][3], bd + SGBL);
                }
#pragma unroll
                for (int mt = 0; mt < 4; mt++)
#pragma unroll
                    for (int nt = 0; nt < 4; nt++) {
                        const unsigned* bph = &bh[nt >> 1][(nt & 1) * 2];
                        const unsigned* bpl = &bl[nt >> 1][(nt & 1) * 2];
                        mma16816(acc[mt][nt], ah[mt], bph);
                        mma16816(acc[mt][nt], al[mt], bph);
                        mma16816(acc[mt][nt], ah[mt], bpl);
                    }
            }
        }
#undef G_ISSUE

        const int r0 = bm + warp_m * 64 + (lane >> 2);
        const int c0 = bn + warp_n * 32 + (lane & 3) * 2;
#pragma unroll
        for (int mt = 0; mt < 4; mt++)
#pragma unroll
            for (int nt = 0; nt < 4; nt++) {
                float* p0 = C + (size_t)(r0 + mt * 16) * N + c0 + nt * 8;
                float* p1 = C + (size_t)(r0 + mt * 16 + 8) * N + c0 + nt * 8;
                *(float2*)p0 = make_float2(acc[mt][nt][0], acc[mt][nt][1]);
                *(float2*)p1 = make_float2(acc[mt][nt][2], acc[mt][nt][3]);
            }

        __syncthreads();   // protect smem buffers before next tile's cp.async
    }
}

// ---------------- RoPE tables (fp64 angles) ------
__global__ void rope_table_kernel()
{
    int idx = blockIdx.x * blockDim.x + threadIdx.x;
    if (idx >= T_ * HALF_) return;
    int t = idx / HALF_, j = idx % HALF_;
    double div  = exp(-(double)(2 * j) * 9.210340371976184 / 128.0);
    float  divf = (float)div;
    float  angf = (float)t * divf;
    g_sin[idx] = (float)sin((double)angf);
    g_cos[idx] = (float)cos((double)angf);
}

// ---------------- fused RoPE + scale + bf16 hi/lo split, head-major layout -------
__device__ __forceinline__ void splitw(float x, __nv_bfloat16* hi, __nv_bfloat16* lo, size_t i) {
    __nv_bfloat16 h = __float2bfloat16(x);
    hi[i] = h;
    lo[i] = __float2bfloat16(x - __bfloat162float(h));
}

__global__ void convert_kernel()
{
    int idx = blockIdx.x * blockDim.x + threadIdx.x;
    int j  = idx & 63;
    int h  = (idx >> 6) & (H_ - 1);
    int bt = idx >> 10;
    int t  = bt & (T_ - 1);
    int b  = bt >> 11;

    float sn = g_sin[t * HALF_ + j];
    float cs = g_cos[t * HALF_ + j];
    const float scale = 0.088388347648318447f;

    size_t src = (size_t)bt * RS_ + h * D_;
    float q1 = g_qkv[src + j],          q2 = g_qkv[src + j + HALF_];
    float k1 = g_qkv[src + C_ + j],     k2 = g_qkv[src + C_ + j + HALF_];
    float v1 = g_qkv[src + 2*C_ + j],   v2 = g_qkv[src + 2*C_ + j + HALF_];

    float qa = (q1 * cs - q2 * sn) * scale;
    float qb = (q2 * cs + q1 * sn) * scale;
    float ka = k1 * cs - k2 * sn;
    float kb = k2 * cs + k1 * sn;

    size_t dst = ((size_t)(b * H_ + h) * T_ + t) * D_;
    splitw(qa, g_qh, g_ql, dst + j);
    splitw(qb, g_qh, g_ql, dst + j + HALF_);
    splitw(ka, g_kh, g_kl, dst + j);
    splitw(kb, g_kh, g_kl, dst + j + HALF_);
    splitw(v1, g_vh, g_vl, dst + j);
    splitw(v2, g_vh, g_vl, dst + j + HALF_);
}

// =================================================================================
//  Tensor-core causal flash attention (unchanged from round 7)
// =================================================================================
#define FKH 0
#define FKL 16384
#define FVH 32768
#define FVL 49152
#define FSTAGE 65536
#define FSM_TOTAL 131072

__device__ __forceinline__ uint32_t fsw(int r, int c) {
    return (uint32_t)(r * 256 + ((((c ^ r) & 7) | (c & 8)) << 4));
}

__global__ void __launch_bounds__(256, 1) flash_mma_kernel()
{
    extern __shared__ char fsm[];
    const uint32_t sb = (uint32_t)__cvta_generic_to_shared(fsm);

    const int i0  = (gridDim.x - 1) - blockIdx.x;
    const int bh  = blockIdx.y;
    const int tid = threadIdx.x;
    const int lane = tid & 31;
    const int w    = tid >> 5;
    const int quad = lane >> 3;
    const int rq   = lane & 7;
    const int lr   = lane >> 2;
    const int lq   = lane & 3;

    const size_t kvbase   = (size_t)bh * (T_ * D_);
    const size_t qrowbase = kvbase + (size_t)i0 * 128 * D_;

    {
        int r  = tid >> 1;
        int cb = (tid & 1) * 8;
        const size_t g = qrowbase + (size_t)r * D_;
#pragma unroll
        for (int j = 0; j < 8; j++) {
            int c = cb + j;
            uint32_t sw = fsw(r, c);
            *(uint4*)(fsm + sw)         = *(const uint4*)(g_qh + g + c * 8);
            *(uint4*)(fsm + 32768 + sw) = *(const uint4*)(g_ql + g + c * 8);
        }
    }
    __syncthreads();

    const int kvr  = tid >> 2;
    const int kvcb = (tid & 3) * 4;
    const int jmax = 2 * i0 + 1;
#define KV_ISSUE(J, BUF) do { \
    const size_t g_ = kvbase + (size_t)((J) * 64 + kvr) * D_; \
    const uint32_t base_ = sb + (BUF) * FSTAGE; \
    _Pragma("unroll") for (int j_ = 0; j_ < 4; j_++) { \
        int c_ = kvcb + j_; \
        uint32_t sw_ = fsw(kvr, c_); \
        CP16(base_ + FKH + sw_, g_kh + g_ + c_ * 8); \
        CP16(base_ + FKL + sw_, g_kl + g_ + c_ * 8); \
        CP16(base_ + FVH + sw_, g_vh + g_ + c_ * 8); \
        CP16(base_ + FVL + sw_, g_vl + g_ + c_ * 8); } \
    CP_COMMIT(); } while (0)

    KV_ISSUE(0, 1);

    const int arow  = 16 * w + (quad & 1) * 8 + rq;
    const int rB    = (quad & 1) * 8 + rq;
    const int cHalf = quad >> 1;

    unsigned qh[8][4], ql[8][4];
#pragma unroll
    for (int kk = 0; kk < 8; kk++) {
        uint32_t aaddr = sb + fsw(arow, 2 * kk + cHalf);
        LDSM_X4(qh[kk][0], qh[kk][1], qh[kk][2], qh[kk][3], aaddr);
        LDSM_X4(ql[kk][0], ql[kk][1], ql[kk][2], ql[kk][3], aaddr + 32768);
    }

    float o[16][4];
#pragma unroll
    for (int dt = 0; dt < 16; dt++)
#pragma unroll
        for (int e = 0; e < 4; e++) o[dt][e] = 0.f;
    float mcur[2] = {-3.4e38f, -3.4e38f};
    float lcur[2] = {0.f, 0.f};

    int buf = 1;
    for (int j0 = 0; j0 <= jmax; j0++) {
        CP_WAIT0();
        __syncthreads();
        if (j0 < jmax) KV_ISSUE(j0 + 1, buf ^ 1);

        const uint32_t kvb = sb + buf * FSTAGE;

        float s[8][4];
#pragma unroll
        for (int nt = 0; nt < 8; nt++)
#pragma unroll
            for (int e = 0; e < 4; e++) s[nt][e] = 0.f;

#pragma unroll
        for (int kk = 0; kk < 8; kk++) {
            const int ca = 2 * kk + cHalf;
            unsigned kh4[4][4], kl4[4][4];
#pragma unroll
            for (int p = 0; p < 4; p++) {
                uint32_t kaddr = kvb + fsw(16 * p + rB, ca);
                LDSM_X4(kh4[p][0], kh4[p][1], kh4[p][2], kh4[p][3], kaddr + FKH);
                LDSM_X4(kl4[p][0], kl4[p][1], kl4[p][2], kl4[p][3], kaddr + FKL);
            }
#pragma unroll
            for (int p = 0; p < 4; p++) {
                unsigned bh0[2] = {kh4[p][0], kh4[p][2]};
                unsigned bh1[2] = {kh4[p][1], kh4[p][3]};
                unsigned bl0[2] = {kl4[p][0], kl4[p][2]};
                unsigned bl1[2] = {kl4[p][1], kl4[p][3]};
                mma16816(s[2*p],   qh[kk], bh0);
                mma16816(s[2*p],   ql[kk], bh0);
                mma16816(s[2*p],   qh[kk], bl0);
                mma16816(s[2*p+1], qh[kk], bh1);
                mma16816(s[2*p+1], ql[kk], bh1);
                mma16816(s[2*p+1], qh[kk], bl1);
            }
        }

        if (j0 >= 2 * i0) {
            const int qr0 = i0 * 128 + 16 * w + lr;
            const int kc0 = j0 * 64 + 2 * lq;
#pragma unroll
            for (int nt = 0; nt < 8; nt++)
#pragma unroll
                for (int e = 0; e < 4; e++) {
                    int r = qr0 + (e >> 1) * 8;
                    int c = kc0 + 8 * nt + (e & 1);
                    if (c > r) s[nt][e] = -3.4e38f;
                }
        }

#pragma unroll
        for (int z = 0; z < 2; z++) {
            float mx = -3.4e38f;
#pragma unroll
            for (int nt = 0; nt < 8; nt++)
                mx = fmaxf(mx, fmaxf(s[nt][2*z], s[nt][2*z+1]));
            mx = fmaxf(mx, __shfl_xor_sync(0xffffffffu, mx, 1));
            mx = fmaxf(mx, __shfl_xor_sync(0xffffffffu, mx, 2));
            float mn = fmaxf(mcur[z], mx);
            float alpha = fast_exp(mcur[z] - mn);
            float ls = 0.f;
#pragma unroll
            for (int nt = 0; nt < 8; nt++) {
                float p0 = fast_exp(s[nt][2*z]   - mn);
                float p1 = fast_exp(s[nt][2*z+1] - mn);
                s[nt][2*z] = p0; s[nt][2*z+1] = p1;
                ls += p0 + p1;
            }
            ls += __shfl_xor_sync(0xffffffffu, ls, 1);
            ls += __shfl_xor_sync(0xffffffffu, ls, 2);
            lcur[z] = lcur[z] * alpha + ls;
            mcur[z] = mn;
#pragma unroll
            for (int dt = 0; dt < 16; dt++) {
                o[dt][2*z]   *= alpha;
                o[dt][2*z+1] *= alpha;
            }
        }

        unsigned ph[4][4], pl[4][4];
#pragma unroll
        for (int kk2 = 0; kk2 < 4; kk2++) {
            split2(s[2*kk2][0],   s[2*kk2][1],   ph[kk2][0], pl[kk2][0]);
            split2(s[2*kk2][2],   s[2*kk2][3],   ph[kk2][1], pl[kk2][1]);
            split2(s[2*kk2+1][0], s[2*kk2+1][1], ph[kk2][2], pl[kk2][2]);
            split2(s[2*kk2+1][2], s[2*kk2+1][3], ph[kk2][3], pl[kk2][3]);
        }

#pragma unroll
        for (int kk2 = 0; kk2 < 4; kk2++) {
            const int rV = 16 * kk2 + rB;
#pragma unroll
            for (int p = 0; p < 8; p++) {
                unsigned vh4[4], vl4[4];
                uint32_t vaddr = kvb + fsw(rV, 2 * p + cHalf);
                LDSM_X4_T(vh4[0], vh4[1], vh4[2], vh4[3], vaddr + FVH);
                LDSM_X4_T(vl4[0], vl4[1], vl4[2], vl4[3], vaddr + FVL);
                mma16816(o[2*p],   ph[kk2], &vh4[0]);
                mma16816(o[2*p],   pl[kk2], &vh4[0]);
                mma16816(o[2*p],   ph[kk2], &vl4[0]);
                mma16816(o[2*p+1], ph[kk2], &vh4[2]);
                mma16816(o[2*p+1], pl[kk2], &vh4[2]);
                mma16816(o[2*p+1], ph[kk2], &vl4[2]);
            }
        }
        buf ^= 1;
    }
#undef KV_ISSUE

    const float inv0 = 1.f / lcur[0];
    const float inv1 = 1.f / lcur[1];
    const size_t obase = ((size_t)bh * T_ + (size_t)i0 * 128 + 16 * w + lr) * D_;
#pragma unroll
    for (int dt = 0; dt < 16; dt++) {
        int col = 8 * dt + 2 * lq;
        unsigned h0, l0, h1, l1;
        split2(o[dt][0] * inv0, o[dt][1] * inv0, h0, l0);
        split2(o[dt][2] * inv1, o[dt][3] * inv1, h1, l1);
        *(unsigned*)(g_oh + obase + col)          = h0;
        *(unsigned*)(g_ol + obase + col)          = l0;
        *(unsigned*)(g_oh + obase + 8 * D_ + col) = h1;
        *(unsigned*)(g_ol + obase + 8 * D_ + col) = l1;
    }
}

// ---------------- launch ----------------
extern "C" void kernel_launch(void* const* d_in, const int* in_sizes, int n_in,
                              void* d_out, int out_size)
{
    const float* x    = (const float*)d_in[0];
    const float* Wqkv = (const float*)d_in[1];
    const float* Wout = (const float*)d_in[2];
    float* out = (float*)d_out;

    float* qkv = nullptr;
    cudaGetSymbolAddress((void**)&qkv, g_qkv);
    __nv_bfloat16 *xh, *xl, *w1h, *w1l, *w2h, *w2l, *oh, *ol;
    cudaGetSymbolAddress((void**)&xh,  g_xh);
    cudaGetSymbolAddress((void**)&xl,  g_xl);
    cudaGetSymbolAddress((void**)&w1h, g_w1h);
    cudaGetSymbolAddress((void**)&w1l, g_w1l);
    cudaGetSymbolAddress((void**)&w2h, g_w2h);
    cudaGetSymbolAddress((void**)&w2l, g_w2l);
    cudaGetSymbolAddress((void**)&oh,  g_oh);
    cudaGetSymbolAddress((void**)&ol,  g_ol);

    cudaFuncSetAttribute(mma_gemm, cudaFuncAttributeMaxDynamicSharedMemorySize, GSM_TOTAL);
    cudaFuncSetAttribute(flash_mma_kernel, cudaFuncAttributeMaxDynamicSharedMemorySize, FSM_TOTAL);

    // 0) pre-split inputs to bf16 hi/lo (x, Wqkv, Wout)
    split_kernel<<<(M_ * C_ / 4) / 256, 256>>>(x, xh, xl);
    split_kernel<<<((size_t)C_ * N1_ / 4) / 256, 256>>>(Wqkv, w1h, w1l);
    split_kernel<<<((size_t)C_ * C_ / 4) / 256, 256>>>(Wout, w2h, w2l);
    // 1) QKV projection (persistent grid)
    mma_gemm<<<GEMM_GRID, 256, GSM_TOTAL>>>(xh, xl, w1h, w1l, qkv, M_, N1_, C_);
    // 2) RoPE tables + fused rope/scale/split/transpose
    rope_table_kernel<<<(T_ * HALF_ + 255) / 256, 256>>>();
    convert_kernel<<<(B_ * T_ * H_ * HALF_) / 256, 256>>>();
    // 3) tensor-core causal flash attention
    flash_mma_kernel<<<dim3(T_ / 128, BH_), 256, FSM_TOTAL>>>();
    // 4) output projection (persistent grid)
    mma_gemm<<<GEMM_GRID, 256, GSM_TOTAL>>>(oh, ol, w2h, w2l, out, M_, C_, C_);
}

// round 9
// speedup vs baseline: 1.0267x; 1.0267x over previous
#include <cuda_runtime.h>
#include <cuda_bf16.h>
#include <cstdint>
#include <math.h>

#define B_   2
#define T_   2048
#define C_   2048
#define H_   16
#define D_   128
#define HALF_ 64
#define M_   (B_*T_)       // 4096
#define N1_  (3*C_)        // 6144
#define RS_  (3*C_)
#define BH_  (B_*H_)       // 32

// ---------------- scratch (device globals) ----------------
__device__ float g_qkv[(size_t)M_ * N1_];
__device__ float g_sin[T_ * HALF_];
__device__ float g_cos[T_ * HALF_];
__device__ __nv_bfloat16 g_qh[(size_t)BH_ * T_ * D_];
__device__ __nv_bfloat16 g_ql[(size_t)BH_ * T_ * D_];
__device__ __nv_bfloat16 g_kh[(size_t)BH_ * T_ * D_];
__device__ __nv_bfloat16 g_kl[(size_t)BH_ * T_ * D_];
__device__ __nv_bfloat16 g_vh[(size_t)BH_ * T_ * D_];
__device__ __nv_bfloat16 g_vl[(size_t)BH_ * T_ * D_];
__device__ __nv_bfloat16 g_xh[(size_t)M_ * C_];
__device__ __nv_bfloat16 g_xl[(size_t)M_ * C_];
__device__ __nv_bfloat16 g_w1h[(size_t)C_ * N1_];
__device__ __nv_bfloat16 g_w1l[(size_t)C_ * N1_];
__device__ __nv_bfloat16 g_w2h[(size_t)C_ * C_];
__device__ __nv_bfloat16 g_w2l[(size_t)C_ * C_];
__device__ __nv_bfloat16 g_oh[(size_t)M_ * C_];
__device__ __nv_bfloat16 g_ol[(size_t)M_ * C_];

// ---------------- fast exp (FFMA-pipe) --------------
__device__ __forceinline__ float fast_exp(float x) {
    x = fmaxf(x, -87.0f);
    float t = x * 1.4426950408889634f;
    int   i = __float2int_rn(t);
    float f = t - (float)i;
    float p =          1.3333558146428443e-3f;
    p = fmaf(p, f, 9.6181291780723730e-3f);
    p = fmaf(p, f, 5.5504108664821580e-2f);
    p = fmaf(p, f, 2.4022650695910072e-1f);
    p = fmaf(p, f, 6.9314718055994531e-1f);
    p = fmaf(p, f, 1.0f);
    return __int_as_float((i + 127) << 23) * p;
}

// ---------------- MMA / LDSM / cp.async primitives ----------------
#define LDSM_X4(R0,R1,R2,R3,ADDR) \
    asm volatile("ldmatrix.sync.aligned.m8n8.x4.shared.b16 {%0,%1,%2,%3}, [%4];" \
                 : "=r"(R0), "=r"(R1), "=r"(R2), "=r"(R3) : "r"(ADDR))
#define LDSM_X4_T(R0,R1,R2,R3,ADDR) \
    asm volatile("ldmatrix.sync.aligned.m8n8.x4.trans.shared.b16 {%0,%1,%2,%3}, [%4];" \
                 : "=r"(R0), "=r"(R1), "=r"(R2), "=r"(R3) : "r"(ADDR))
#define CP16(DST, SRC) \
    asm volatile("cp.async.cg.shared.global [%0], [%1], 16;" :: "r"(DST), "l"(SRC))
#define CP_COMMIT()  asm volatile("cp.async.commit_group;" ::: "memory")
#define CP_WAIT0()   asm volatile("cp.async.wait_group 0;" ::: "memory")
#define CP_WAIT1()   asm volatile("cp.async.wait_group 1;" ::: "memory")

__device__ __forceinline__ void mma16816(float* d, const unsigned* a, const unsigned* b) {
    asm volatile(
        "mma.sync.aligned.m16n8k16.row.col.f32.bf16.bf16.f32 "
        "{%0,%1,%2,%3}, {%4,%5,%6,%7}, {%8,%9}, {%0,%1,%2,%3};"
        : "+f"(d[0]), "+f"(d[1]), "+f"(d[2]), "+f"(d[3])
        : "r"(a[0]), "r"(a[1]), "r"(a[2]), "r"(a[3]), "r"(b[0]), "r"(b[1]));
}

__device__ __forceinline__ void split2(float x, float y, unsigned& hi, unsigned& lo) {
    __nv_bfloat162 h2 = __floats2bfloat162_rn(x, y);
    float hx = __bfloat162float(h2.x);
    float hy = __bfloat162float(h2.y);
    __nv_bfloat162 l2 = __floats2bfloat162_rn(x - hx, y - hy);
    hi = *reinterpret_cast<unsigned*>(&h2);
    lo = *reinterpret_cast<unsigned*>(&l2);
}

// ---------------- pre-pass: elementwise fp32 -> bf16 hi/lo split ----------------
__global__ void split_kernel(const float* __restrict__ src,
                             __nv_bfloat16* __restrict__ th,
                             __nv_bfloat16* __restrict__ tl)
{
    size_t i = ((size_t)blockIdx.x * blockDim.x + threadIdx.x) * 4;
    float4 v = *(const float4*)(src + i);
    unsigned h0, l0, h1, l1;
    split2(v.x, v.y, h0, l0);
    split2(v.z, v.w, h1, l1);
    *(uint2*)(th + i) = make_uint2(h0, h1);
    *(uint2*)(tl + i) = make_uint2(l0, l1);
}

// =================================================================================
//  bf16x3 split-precision tensor-core GEMM (round-7 version: non-persistent,
//  cp.async 3-stage, BK=32, 2 CTAs/SM)
// =================================================================================
#define SGBH  16384
#define SGBL  24576
#define STAGE_ 32768
#define NSTAGE 3
#define GSM_TOTAL (NSTAGE * STAGE_)   // 98304

__global__ void __launch_bounds__(256, 2) mma_gemm(const __nv_bfloat16* __restrict__ Ah,
                                                   const __nv_bfloat16* __restrict__ Al,
                                                   const __nv_bfloat16* __restrict__ Bh,
                                                   const __nv_bfloat16* __restrict__ Bl,
                                                   float* __restrict__ C,
                                                   int M, int N, int K)
{
    extern __shared__ char smem[];
    const uint32_t smem_u32 = (uint32_t)__cvta_generic_to_shared(smem);

    const int tid  = threadIdx.x;
    const int lane = tid & 31;
    const int wid  = tid >> 5;
    const int warp_m = wid & 1;
    const int warp_n = wid >> 1;
    const int quad = lane >> 3;
    const int rq   = lane & 7;

    const int bm = blockIdx.y * 128;
    const int bn = blockIdx.x * 128;

    uint32_t swA[4], swB[4];
    const __nv_bfloat16* pA[4];
    const __nv_bfloat16* pB[4];
#pragma unroll
    for (int i = 0; i < 4; i++) {
        int ia = i * 256 + tid;
        int ra = ia >> 3, ca = ia & 7;
        swA[i] = ra * 128 + ((ca ^ (ra & 7)) << 4);
        pA[i]  = (ca < 4 ? Ah : Al) + (size_t)(bm + ra) * K + (ca & 3) * 8;
        int hilo = ia >> 9;
        int rem  = ia & 511;
        int rb = rem >> 4, cb = rem & 15;
        swB[i] = (hilo ? SGBL : SGBH) + rb * 256 + (((cb & 8) | ((cb & 7) ^ (rb & 7))) << 4);
        pB[i]  = (hilo ? Bl : Bh) + (size_t)rb * N + bn + cb * 8;
    }

    const int aRowL = warp_m * 64 + (quad & 1) * 8 + rq;
    const int kHalf = quad >> 1;
    const int arow7 = aRowL & 7;
    const int arowByte = aRowL * 128;

    const int kL = (quad & 1) * 8 + rq;
    int nbswp[2];
#pragma unroll
    for (int p = 0; p < 2; p++) {
        int nb = warp_n * 4 + (quad >> 1) + p * 2;
        nbswp[p] = (nb & 8) | ((nb & 7) ^ (kL & 7));
    }
    const int bByteBase = kL * 256;

    float acc[4][4][4];
#pragma unroll
    for (int mt = 0; mt < 4; mt++)
#pragma unroll
        for (int nt = 0; nt < 4; nt++)
#pragma unroll
            for (int c = 0; c < 4; c++) acc[mt][nt][c] = 0.f;

#define G_ISSUE(k0, buf) do { \
    const uint32_t b_ = smem_u32 + (buf) * STAGE_; \
    _Pragma("unroll") for (int i = 0; i < 4; i++) { \
        CP16(b_ + swA[i], pA[i] + (k0)); \
        CP16(b_ + swB[i], pB[i] + (size_t)(k0) * N); } \
    CP_COMMIT(); } while (0)

    const int KT = K >> 5;
    G_ISSUE(0, 0);
    G_ISSUE(32, 1);

    for (int kt = 0; kt < KT; kt++) {
        if (kt + 1 < KT) { CP_WAIT1(); } else { CP_WAIT0(); }
        __syncthreads();
        if (kt + 2 < KT) G_ISSUE((kt + 2) * 32, (kt + 2) % NSTAGE);

        const uint32_t sbase = smem_u32 + (kt % NSTAGE) * STAGE_;
#pragma unroll
        for (int kk = 0; kk < 2; kk++) {
            unsigned ah[4][4], al[4][4], bh[2][4], bl[2][4];
            const int chi = 2 * kk + kHalf;
            const int asw_h = ((chi)     ^ arow7) << 4;
            const int asw_l = ((chi + 4) ^ arow7) << 4;
#pragma unroll
            for (int mt = 0; mt < 4; mt++) {
                uint32_t ad = sbase + arowByte + mt * 2048;
                LDSM_X4(ah[mt][0], ah[mt][1], ah[mt][2], ah[mt][3], ad + asw_h);
                LDSM_X4(al[mt][0], al[mt][1], al[mt][2], al[mt][3], ad + asw_l);
            }
#pragma unroll
            for (int p = 0; p < 2; p++) {
                uint32_t bd = sbase + kk * 4096 + bByteBase + nbswp[p] * 16;
                LDSM_X4_T(bh[p][0], bh[p][1], bh[p][2], bh[p][3], bd + SGBH);
                LDSM_X4_T(bl[p][0], bl[p][1], bl[p][2], bl[p][3], bd + SGBL);
            }
#pragma unroll
            for (int mt = 0; mt < 4; mt++)
#pragma unroll
                for (int nt = 0; nt < 4; nt++) {
                    const unsigned* bph = &bh[nt >> 1][(nt & 1) * 2];
                    const unsigned* bpl = &bl[nt >> 1][(nt & 1) * 2];
                    mma16816(acc[mt][nt], ah[mt], bph);
                    mma16816(acc[mt][nt], al[mt], bph);
                    mma16816(acc[mt][nt], ah[mt], bpl);
                }
        }
    }
#undef G_ISSUE

    __syncthreads();
    const int r0 = bm + warp_m * 64 + (lane >> 2);
    const int c0 = bn + warp_n * 32 + (lane & 3) * 2;
#pragma unroll
    for (int mt = 0; mt < 4; mt++)
#pragma unroll
        for (int nt = 0; nt < 4; nt++) {
            float* p0 = C + (size_t)(r0 + mt * 16) * N + c0 + nt * 8;
            float* p1 = C + (size_t)(r0 + mt * 16 + 8) * N + c0 + nt * 8;
            *(float2*)p0 = make_float2(acc[mt][nt][0], acc[mt][nt][1]);
            *(float2*)p1 = make_float2(acc[mt][nt][2], acc[mt][nt][3]);
        }
}

// ---------------- RoPE tables (fp64 angles) ------
__global__ void rope_table_kernel()
{
    int idx = blockIdx.x * blockDim.x + threadIdx.x;
    if (idx >= T_ * HALF_) return;
    int t = idx / HALF_, j = idx % HALF_;
    double div  = exp(-(double)(2 * j) * 9.210340371976184 / 128.0);
    float  divf = (float)div;
    float  angf = (float)t * divf;
    g_sin[idx] = (float)sin((double)angf);
    g_cos[idx] = (float)cos((double)angf);
}

// ---------------- fused RoPE + scale + bf16 hi/lo split ----------------
__device__ __forceinline__ void splitw(float x, __nv_bfloat16* hi, __nv_bfloat16* lo, size_t i) {
    __nv_bfloat16 h = __float2bfloat16(x);
    hi[i] = h;
    lo[i] = __float2bfloat16(x - __bfloat162float(h));
}

__global__ void convert_kernel()
{
    int idx = blockIdx.x * blockDim.x + threadIdx.x;
    int j  = idx & 63;
    int h  = (idx >> 6) & (H_ - 1);
    int bt = idx >> 10;
    int t  = bt & (T_ - 1);
    int b  = bt >> 11;

    float sn = g_sin[t * HALF_ + j];
    float cs = g_cos[t * HALF_ + j];
    const float scale = 0.088388347648318447f;

    size_t src = (size_t)bt * RS_ + h * D_;
    float q1 = g_qkv[src + j],          q2 = g_qkv[src + j + HALF_];
    float k1 = g_qkv[src + C_ + j],     k2 = g_qkv[src + C_ + j + HALF_];
    float v1 = g_qkv[src + 2*C_ + j],   v2 = g_qkv[src + 2*C_ + j + HALF_];

    float qa = (q1 * cs - q2 * sn) * scale;
    float qb = (q2 * cs + q1 * sn) * scale;
    float ka = k1 * cs - k2 * sn;
    float kb = k2 * cs + k1 * sn;

    size_t dst = ((size_t)(b * H_ + h) * T_ + t) * D_;
    splitw(qa, g_qh, g_ql, dst + j);
    splitw(qb, g_qh, g_ql, dst + j + HALF_);
    splitw(ka, g_kh, g_kl, dst + j);
    splitw(kb, g_kh, g_kl, dst + j + HALF_);
    splitw(v1, g_vh, g_vl, dst + j);
    splitw(v2, g_vh, g_vl, dst + j + HALF_);
}

// =================================================================================
//  Tensor-core causal flash attention, 2-tile softmax/MMA software pipeline:
//  while softmax(tile j) runs on the FMA pipe, QK(tile j+1) runs on the tensor pipe.
//  3-buffer KV ring (192KB smem), Q fragments in registers, one barrier per iter.
// =================================================================================
#define FKH 0
#define FKL 16384
#define FVH 32768
#define FVL 49152
#define FSTAGE 65536
#define FSM_TOTAL 196608

__device__ __forceinline__ uint32_t fsw(int r, int c) {
    return (uint32_t)(r * 256 + ((((c ^ r) & 7) | (c & 8)) << 4));
}

// S = Q K^T for one 64-key tile (bf16x3)
__device__ __forceinline__ void fqk(float (*s)[4], const unsigned (*qh)[4], const unsigned (*ql)[4],
                                    uint32_t kvb, int rB, int cHalf)
{
#pragma unroll
    for (int nt = 0; nt < 8; nt++)
#pragma unroll
        for (int e = 0; e < 4; e++) s[nt][e] = 0.f;
#pragma unroll
    for (int kk = 0; kk < 8; kk++) {
        const int ca = 2 * kk + cHalf;
        unsigned kh4[4][4], kl4[4][4];
#pragma unroll
        for (int p = 0; p < 4; p++) {
            uint32_t kaddr = kvb + fsw(16 * p + rB, ca);
            LDSM_X4(kh4[p][0], kh4[p][1], kh4[p][2], kh4[p][3], kaddr + FKH);
            LDSM_X4(kl4[p][0], kl4[p][1], kl4[p][2], kl4[p][3], kaddr + FKL);
        }
#pragma unroll
        for (int p = 0; p < 4; p++) {
            unsigned bh0[2] = {kh4[p][0], kh4[p][2]};
            unsigned bh1[2] = {kh4[p][1], kh4[p][3]};
            unsigned bl0[2] = {kl4[p][0], kl4[p][2]};
            unsigned bl1[2] = {kl4[p][1], kl4[p][3]};
            mma16816(s[2*p],   qh[kk], bh0);
            mma16816(s[2*p],   ql[kk], bh0);
            mma16816(s[2*p],   qh[kk], bl0);
            mma16816(s[2*p+1], qh[kk], bh1);
            mma16816(s[2*p+1], ql[kk], bh1);
            mma16816(s[2*p+1], qh[kk], bl1);
        }
    }
}

// mask + online softmax + pack P (hi/lo) + rescale o
__device__ __forceinline__ void fsoftmax(float (*s)[4], int jt, int i0, int w, int lr, int lq,
                                         float* mcur, float* lcur, float (*o)[4],
                                         unsigned (*ph)[4], unsigned (*pl)[4])
{
    if (jt >= 2 * i0) {
        const int qr0 = i0 * 128 + 16 * w + lr;
        const int kc0 = jt * 64 + 2 * lq;
#pragma unroll
        for (int nt = 0; nt < 8; nt++)
#pragma unroll
            for (int e = 0; e < 4; e++) {
                int r = qr0 + (e >> 1) * 8;
                int c = kc0 + 8 * nt + (e & 1);
                if (c > r) s[nt][e] = -3.4e38f;
            }
    }
#pragma unroll
    for (int z = 0; z < 2; z++) {
        float mx = -3.4e38f;
#pragma unroll
        for (int nt = 0; nt < 8; nt++)
            mx = fmaxf(mx, fmaxf(s[nt][2*z], s[nt][2*z+1]));
        mx = fmaxf(mx, __shfl_xor_sync(0xffffffffu, mx, 1));
        mx = fmaxf(mx, __shfl_xor_sync(0xffffffffu, mx, 2));
        float mn = fmaxf(mcur[z], mx);
        float alpha = fast_exp(mcur[z] - mn);
        float ls = 0.f;
#pragma unroll
        for (int nt = 0; nt < 8; nt++) {
            float p0 = fast_exp(s[nt][2*z]   - mn);
            float p1 = fast_exp(s[nt][2*z+1] - mn);
            s[nt][2*z] = p0; s[nt][2*z+1] = p1;
            ls += p0 + p1;
        }
        ls += __shfl_xor_sync(0xffffffffu, ls, 1);
        ls += __shfl_xor_sync(0xffffffffu, ls, 2);
        lcur[z] = lcur[z] * alpha + ls;
        mcur[z] = mn;
#pragma unroll
        for (int dt = 0; dt < 16; dt++) {
            o[dt][2*z]   *= alpha;
            o[dt][2*z+1] *= alpha;
        }
    }
#pragma unroll
    for (int kk2 = 0; kk2 < 4; kk2++) {
        split2(s[2*kk2][0],   s[2*kk2][1],   ph[kk2][0], pl[kk2][0]);
        split2(s[2*kk2][2],   s[2*kk2][3],   ph[kk2][1], pl[kk2][1]);
        split2(s[2*kk2+1][0], s[2*kk2+1][1], ph[kk2][2], pl[kk2][2]);
        split2(s[2*kk2+1][2], s[2*kk2+1][3], ph[kk2][3], pl[kk2][3]);
    }
}

// O += P V (bf16x3)
__device__ __forceinline__ void fpv(float (*o)[4], const unsigned (*ph)[4], const unsigned (*pl)[4],
                                    uint32_t kvb, int rB, int cHalf)
{
#pragma unroll
    for (int kk2 = 0; kk2 < 4; kk2++) {
        const int rV = 16 * kk2 + rB;
#pragma unroll
        for (int p = 0; p < 8; p++) {
            unsigned vh4[4], vl4[4];
            uint32_t vaddr = kvb + fsw(rV, 2 * p + cHalf);
            LDSM_X4_T(vh4[0], vh4[1], vh4[2], vh4[3], vaddr + FVH);
            LDSM_X4_T(vl4[0], vl4[1], vl4[2], vl4[3], vaddr + FVL);
            mma16816(o[2*p],   ph[kk2], &vh4[0]);
            mma16816(o[2*p],   pl[kk2], &vh4[0]);
            mma16816(o[2*p],   ph[kk2], &vl4[0]);
            mma16816(o[2*p+1], ph[kk2], &vh4[2]);
            mma16816(o[2*p+1], pl[kk2], &vh4[2]);
            mma16816(o[2*p+1], ph[kk2], &vl4[2]);
        }
    }
}

__global__ void __launch_bounds__(256, 1) flash_mma_kernel()
{
    extern __shared__ char fsm[];
    const uint32_t sb = (uint32_t)__cvta_generic_to_shared(fsm);

    const int i0  = (gridDim.x - 1) - blockIdx.x;   // heavy tiles first
    const int bh  = blockIdx.y;
    const int tid = threadIdx.x;
    const int lane = tid & 31;
    const int w    = tid >> 5;
    const int quad = lane >> 3;
    const int rq   = lane & 7;
    const int lr   = lane >> 2;
    const int lq   = lane & 3;

    const size_t kvbase   = (size_t)bh * (T_ * D_);
    const size_t qrowbase = kvbase + (size_t)i0 * 128 * D_;

    // ---- stage Q tiles in buffer 0 (hi at 0, lo at +32768) ----
    {
        int r  = tid >> 1;
        int cb = (tid & 1) * 8;
        const size_t g = qrowbase + (size_t)r * D_;
#pragma unroll
        for (int j = 0; j < 8; j++) {
            int c = cb + j;
            uint32_t sw = fsw(r, c);
            *(uint4*)(fsm + sw)         = *(const uint4*)(g_qh + g + c * 8);
            *(uint4*)(fsm + 32768 + sw) = *(const uint4*)(g_ql + g + c * 8);
        }
    }
    __syncthreads();

    const int kvr  = tid >> 2;
    const int kvcb = (tid & 3) * 4;
    const int jmax = 2 * i0 + 1;
#define KV_ISSUE(J, BUF) do { \
    const size_t g_ = kvbase + (size_t)((J) * 64 + kvr) * D_; \
    const uint32_t base_ = sb + (BUF) * FSTAGE; \
    _Pragma("unroll") for (int j_ = 0; j_ < 4; j_++) { \
        int c_ = kvcb + j_; \
        uint32_t sw_ = fsw(kvr, c_); \
        CP16(base_ + FKH + sw_, g_kh + g_ + c_ * 8); \
        CP16(base_ + FKL + sw_, g_kl + g_ + c_ * 8); \
        CP16(base_ + FVH + sw_, g_vh + g_ + c_ * 8); \
        CP16(base_ + FVL + sw_, g_vl + g_ + c_ * 8); } \
    CP_COMMIT(); } while (0)

    // KV(j) lives in buffer (j+1)%3. KV(2) reuses buffer 0 after Q frags are read.
    KV_ISSUE(0, 1);
    KV_ISSUE(1, 2);

    // ---- Q fragments into registers (reads buffer 0) ----
    const int arow  = 16 * w + (quad & 1) * 8 + rq;
    const int rB    = (quad & 1) * 8 + rq;
    const int cHalf = quad >> 1;

    unsigned qh[8][4], ql[8][4];
#pragma unroll
    for (int kk = 0; kk < 8; kk++) {
        uint32_t aaddr = sb + fsw(arow, 2 * kk + cHalf);
        LDSM_X4(qh[kk][0], qh[kk][1], qh[kk][2], qh[kk][3], aaddr);
        LDSM_X4(ql[kk][0], ql[kk][1], ql[kk][2], ql[kk][3], aaddr + 32768);
    }

    float o[16][4];
#pragma unroll
    for (int dt = 0; dt < 16; dt++)
#pragma unroll
        for (int e = 0; e < 4; e++) o[dt][e] = 0.f;
    float mcur[2] = {-3.4e38f, -3.4e38f};
    float lcur[2] = {0.f, 0.f};

    // ---- prologue: scores(0) ----
    CP_WAIT1();              // KV(0) landed
    __syncthreads();
    float s_a[8][4], s_b[8][4];
    fqk(s_a, qh, ql, sb + 1 * FSTAGE, rB, cHalf);

    int b0 = 1, b1 = 2, b2 = 0;   // bufKV(j), bufKV(j+1), next-free
    unsigned ph[4][4], pl[4][4];

    // ---- pipelined mainloop: QK(j+1) overlaps softmax(j) ----
    for (int j = 0; j < jmax; j++) {
        CP_WAIT0();          // KV(j+1) landed
        __syncthreads();     // all warps done reading buffer b2 (V(j-1))
        if (j + 2 <= jmax) KV_ISSUE(j + 2, b2);

        // tensor pipe: S_b = QK(j+1); FMA pipe: softmax(S_a) — independent, interleaved
        fqk(s_b, qh, ql, sb + b1 * FSTAGE, rB, cHalf);
        fsoftmax(s_a, j, i0, w, lr, lq, mcur, lcur, o, ph, pl);
        fpv(o, ph, pl, sb + b0 * FSTAGE, rB, cHalf);

#pragma unroll
        for (int nt = 0; nt < 8; nt++)
#pragma unroll
            for (int e = 0; e < 4; e++) s_a[nt][e] = s_b[nt][e];
        int t_ = b0; b0 = b1; b1 = b2; b2 = t_;
    }

    // ---- peeled final tile ----
    fsoftmax(s_a, jmax, i0, w, lr, lq, mcur, lcur, o, ph, pl);
    fpv(o, ph, pl, sb + b0 * FSTAGE, rB, cHalf);
#undef KV_ISSUE

    // ---- epilogue: O /= l, write bf16 hi/lo splits (flat B,H,T,D) ----
    const float inv0 = 1.f / lcur[0];
    const float inv1 = 1.f / lcur[1];
    const size_t obase = ((size_t)bh * T_ + (size_t)i0 * 128 + 16 * w + lr) * D_;
#pragma unroll
    for (int dt = 0; dt < 16; dt++) {
        int col = 8 * dt + 2 * lq;
        unsigned h0, l0, h1, l1;
        split2(o[dt][0] * inv0, o[dt][1] * inv0, h0, l0);
        split2(o[dt][2] * inv1, o[dt][3] * inv1, h1, l1);
        *(unsigned*)(g_oh + obase + col)          = h0;
        *(unsigned*)(g_ol + obase + col)          = l0;
        *(unsigned*)(g_oh + obase + 8 * D_ + col) = h1;
        *(unsigned*)(g_ol + obase + 8 * D_ + col) = l1;
    }
}

// ---------------- launch ----------------
extern "C" void kernel_launch(void* const* d_in, const int* in_sizes, int n_in,
                              void* d_out, int out_size)
{
    const float* x    = (const float*)d_in[0];
    const float* Wqkv = (const float*)d_in[1];
    const float* Wout = (const float*)d_in[2];
    float* out = (float*)d_out;

    float* qkv = nullptr;
    cudaGetSymbolAddress((void**)&qkv, g_qkv);
    __nv_bfloat16 *xh, *xl, *w1h, *w1l, *w2h, *w2l, *oh, *ol;
    cudaGetSymbolAddress((void**)&xh,  g_xh);
    cudaGetSymbolAddress((void**)&xl,  g_xl);
    cudaGetSymbolAddress((void**)&w1h, g_w1h);
    cudaGetSymbolAddress((void**)&w1l, g_w1l);
    cudaGetSymbolAddress((void**)&w2h, g_w2h);
    cudaGetSymbolAddress((void**)&w2l, g_w2l);
    cudaGetSymbolAddress((void**)&oh,  g_oh);
    cudaGetSymbolAddress((void**)&ol,  g_ol);

    cudaFuncSetAttribute(mma_gemm, cudaFuncAttributeMaxDynamicSharedMemorySize, GSM_TOTAL);
    cudaFuncSetAttribute(flash_mma_kernel, cudaFuncAttributeMaxDynamicSharedMemorySize, FSM_TOTAL);

    // 0) pre-split inputs to bf16 hi/lo
    split_kernel<<<(M_ * C_ / 4) / 256, 256>>>(x, xh, xl);
    split_kernel<<<((size_t)C_ * N1_ / 4) / 256, 256>>>(Wqkv, w1h, w1l);
    split_kernel<<<((size_t)C_ * C_ / 4) / 256, 256>>>(Wout, w2h, w2l);
    // 1) QKV projection
    mma_gemm<<<dim3(N1_ / 128, M_ / 128), 256, GSM_TOTAL>>>(xh, xl, w1h, w1l, qkv, M_, N1_, C_);
    // 2) RoPE tables + fused rope/scale/split/transpose
    rope_table_kernel<<<(T_ * HALF_ + 255) / 256, 256>>>();
    convert_kernel<<<(B_ * T_ * H_ * HALF_) / 256, 256>>>();
    // 3) pipelined tensor-core causal flash attention
    flash_mma_kernel<<<dim3(T_ / 128, BH_), 256, FSM_TOTAL>>>();
    // 4) output projection
    mma_gemm<<<dim3(C_ / 128, M_ / 128), 256, GSM_TOTAL>>>(oh, ol, w2h, w2l, out, M_, C_, C_);
}

// round 10
// speedup vs baseline: 1.0372x; 1.0102x over previous
#include <cuda_runtime.h>
#include <cuda_bf16.h>
#include <cstdint>
#include <math.h>

#define B_   2
#define T_   2048
#define C_   2048
#define H_   16
#define D_   128
#define HALF_ 64
#define M_   (B_*T_)       // 4096
#define N1_  (3*C_)        // 6144
#define BH_  (B_*H_)       // 32

// ---------------- scratch (device globals) ----------------
__device__ float g_sin[T_ * HALF_];
__device__ float g_cos[T_ * HALF_];
__device__ __nv_bfloat16 g_qh[(size_t)BH_ * T_ * D_];  // roped+scaled Q hi/lo, head-major
__device__ __nv_bfloat16 g_ql[(size_t)BH_ * T_ * D_];
__device__ __nv_bfloat16 g_kh[(size_t)BH_ * T_ * D_];
__device__ __nv_bfloat16 g_kl[(size_t)BH_ * T_ * D_];
__device__ __nv_bfloat16 g_vh[(size_t)BH_ * T_ * D_];
__device__ __nv_bfloat16 g_vl[(size_t)BH_ * T_ * D_];
__device__ __nv_bfloat16 g_xh[(size_t)M_ * C_];
__device__ __nv_bfloat16 g_xl[(size_t)M_ * C_];
__device__ __nv_bfloat16 g_w1h[(size_t)C_ * N1_];
__device__ __nv_bfloat16 g_w1l[(size_t)C_ * N1_];
__device__ __nv_bfloat16 g_w2h[(size_t)C_ * C_];
__device__ __nv_bfloat16 g_w2l[(size_t)C_ * C_];
__device__ __nv_bfloat16 g_oh[(size_t)M_ * C_];
__device__ __nv_bfloat16 g_ol[(size_t)M_ * C_];

// ---------------- fast exp (FFMA-pipe) --------------
__device__ __forceinline__ float fast_exp(float x) {
    x = fmaxf(x, -87.0f);
    float t = x * 1.4426950408889634f;
    int   i = __float2int_rn(t);
    float f = t - (float)i;
    float p =          1.3333558146428443e-3f;
    p = fmaf(p, f, 9.6181291780723730e-3f);
    p = fmaf(p, f, 5.5504108664821580e-2f);
    p = fmaf(p, f, 2.4022650695910072e-1f);
    p = fmaf(p, f, 6.9314718055994531e-1f);
    p = fmaf(p, f, 1.0f);
    return __int_as_float((i + 127) << 23) * p;
}

// ---------------- MMA / LDSM / cp.async primitives ----------------
#define LDSM_X4(R0,R1,R2,R3,ADDR) \
    asm volatile("ldmatrix.sync.aligned.m8n8.x4.shared.b16 {%0,%1,%2,%3}, [%4];" \
                 : "=r"(R0), "=r"(R1), "=r"(R2), "=r"(R3) : "r"(ADDR))
#define LDSM_X4_T(R0,R1,R2,R3,ADDR) \
    asm volatile("ldmatrix.sync.aligned.m8n8.x4.trans.shared.b16 {%0,%1,%2,%3}, [%4];" \
                 : "=r"(R0), "=r"(R1), "=r"(R2), "=r"(R3) : "r"(ADDR))
#define CP16(DST, SRC) \
    asm volatile("cp.async.cg.shared.global [%0], [%1], 16;" :: "r"(DST), "l"(SRC))
#define CP_COMMIT()  asm volatile("cp.async.commit_group;" ::: "memory")
#define CP_WAIT0()   asm volatile("cp.async.wait_group 0;" ::: "memory")
#define CP_WAIT1()   asm volatile("cp.async.wait_group 1;" ::: "memory")

__device__ __forceinline__ void mma16816(float* d, const unsigned* a, const unsigned* b) {
    asm volatile(
        "mma.sync.aligned.m16n8k16.row.col.f32.bf16.bf16.f32 "
        "{%0,%1,%2,%3}, {%4,%5,%6,%7}, {%8,%9}, {%0,%1,%2,%3};"
        : "+f"(d[0]), "+f"(d[1]), "+f"(d[2]), "+f"(d[3])
        : "r"(a[0]), "r"(a[1]), "r"(a[2]), "r"(a[3]), "r"(b[0]), "r"(b[1]));
}

__device__ __forceinline__ void split2(float x, float y, unsigned& hi, unsigned& lo) {
    __nv_bfloat162 h2 = __floats2bfloat162_rn(x, y);
    float hx = __bfloat162float(h2.x);
    float hy = __bfloat162float(h2.y);
    __nv_bfloat162 l2 = __floats2bfloat162_rn(x - hx, y - hy);
    hi = *reinterpret_cast<unsigned*>(&h2);
    lo = *reinterpret_cast<unsigned*>(&l2);
}

__device__ __forceinline__ void splitw(float x, __nv_bfloat16* hi, __nv_bfloat16* lo, size_t i) {
    __nv_bfloat16 h = __float2bfloat16(x);
    hi[i] = h;
    lo[i] = __float2bfloat16(x - __bfloat162float(h));
}

// ---------------- pre-pass: elementwise fp32 -> bf16 hi/lo split ----------------
__global__ void split_kernel(const float* __restrict__ src,
                             __nv_bfloat16* __restrict__ th,
                             __nv_bfloat16* __restrict__ tl)
{
    size_t i = ((size_t)blockIdx.x * blockDim.x + threadIdx.x) * 4;
    float4 v = *(const float4*)(src + i);
    unsigned h0, l0, h1, l1;
    split2(v.x, v.y, h0, l0);
    split2(v.z, v.w, h1, l1);
    *(uint2*)(th + i) = make_uint2(h0, h1);
    *(uint2*)(tl + i) = make_uint2(l0, l1);
}

// ---------------- RoPE tables (fp64 angles) ------
__global__ void rope_table_kernel()
{
    int idx = blockIdx.x * blockDim.x + threadIdx.x;
    if (idx >= T_ * HALF_) return;
    int t = idx / HALF_, j = idx % HALF_;
    double div  = exp(-(double)(2 * j) * 9.210340371976184 / 128.0);
    float  divf = (float)div;
    float  angf = (float)t * divf;
    g_sin[idx] = (float)sin((double)angf);
    g_cos[idx] = (float)cos((double)angf);
}

// =================================================================================
//  bf16x3 split-precision tensor-core GEMM (cp.async 3-stage, BK=32, 2 CTAs/SM).
//  mode 0: plain fp32 C epilogue (GEMM2).
//  mode 1: fused QKV epilogue — per-tile (one head, one region): V -> direct split;
//          Q/K -> smem roundtrip, RoPE (+1/sqrt(D) for Q), split; head-major out.
// =================================================================================
#define SGBH  16384
#define SGBL  24576
#define STAGE_ 32768
#define NSTAGE 3
#define GSM_TOTAL (NSTAGE * STAGE_)   // 98304 >= 128*132*4 epilogue staging

__global__ void __launch_bounds__(256, 2) mma_gemm(const __nv_bfloat16* __restrict__ Ah,
                                                   const __nv_bfloat16* __restrict__ Al,
                                                   const __nv_bfloat16* __restrict__ Bh,
                                                   const __nv_bfloat16* __restrict__ Bl,
                                                   float* __restrict__ C,
                                                   int M, int N, int K, int mode)
{
    extern __shared__ char smem[];
    const uint32_t smem_u32 = (uint32_t)__cvta_generic_to_shared(smem);

    const int tid  = threadIdx.x;
    const int lane = tid & 31;
    const int wid  = tid >> 5;
    const int warp_m = wid & 1;
    const int warp_n = wid >> 1;
    const int quad = lane >> 3;
    const int rq   = lane & 7;

    const int bm = blockIdx.y * 128;
    const int bn = blockIdx.x * 128;

    uint32_t swA[4], swB[4];
    const __nv_bfloat16* pA[4];
    const __nv_bfloat16* pB[4];
#pragma unroll
    for (int i = 0; i < 4; i++) {
        int ia = i * 256 + tid;
        int ra = ia >> 3, ca = ia & 7;
        swA[i] = ra * 128 + ((ca ^ (ra & 7)) << 4);
        pA[i]  = (ca < 4 ? Ah : Al) + (size_t)(bm + ra) * K + (ca & 3) * 8;
        int hilo = ia >> 9;
        int rem  = ia & 511;
        int rb = rem >> 4, cb = rem & 15;
        swB[i] = (hilo ? SGBL : SGBH) + rb * 256 + (((cb & 8) | ((cb & 7) ^ (rb & 7))) << 4);
        pB[i]  = (hilo ? Bl : Bh) + (size_t)rb * N + bn + cb * 8;
    }

    const int aRowL = warp_m * 64 + (quad & 1) * 8 + rq;
    const int kHalf = quad >> 1;
    const int arow7 = aRowL & 7;
    const int arowByte = aRowL * 128;

    const int kL = (quad & 1) * 8 + rq;
    int nbswp[2];
#pragma unroll
    for (int p = 0; p < 2; p++) {
        int nb = warp_n * 4 + (quad >> 1) + p * 2;
        nbswp[p] = (nb & 8) | ((nb & 7) ^ (kL & 7));
    }
    const int bByteBase = kL * 256;

    float acc[4][4][4];
#pragma unroll
    for (int mt = 0; mt < 4; mt++)
#pragma unroll
        for (int nt = 0; nt < 4; nt++)
#pragma unroll
            for (int c = 0; c < 4; c++) acc[mt][nt][c] = 0.f;

#define G_ISSUE(k0, buf) do { \
    const uint32_t b_ = smem_u32 + (buf) * STAGE_; \
    _Pragma("unroll") for (int i = 0; i < 4; i++) { \
        CP16(b_ + swA[i], pA[i] + (k0)); \
        CP16(b_ + swB[i], pB[i] + (size_t)(k0) * N); } \
    CP_COMMIT(); } while (0)

    const int KT = K >> 5;
    G_ISSUE(0, 0);
    G_ISSUE(32, 1);

    for (int kt = 0; kt < KT; kt++) {
        if (kt + 1 < KT) { CP_WAIT1(); } else { CP_WAIT0(); }
        __syncthreads();
        if (kt + 2 < KT) G_ISSUE((kt + 2) * 32, (kt + 2) % NSTAGE);

        const uint32_t sbase = smem_u32 + (kt % NSTAGE) * STAGE_;
#pragma unroll
        for (int kk = 0; kk < 2; kk++) {
            unsigned ah[4][4], al[4][4], bh[2][4], bl[2][4];
            const int chi = 2 * kk + kHalf;
            const int asw_h = ((chi)     ^ arow7) << 4;
            const int asw_l = ((chi + 4) ^ arow7) << 4;
#pragma unroll
            for (int mt = 0; mt < 4; mt++) {
                uint32_t ad = sbase + arowByte + mt * 2048;
                LDSM_X4(ah[mt][0], ah[mt][1], ah[mt][2], ah[mt][3], ad + asw_h);
                LDSM_X4(al[mt][0], al[mt][1], al[mt][2], al[mt][3], ad + asw_l);
            }
#pragma unroll
            for (int p = 0; p < 2; p++) {
                uint32_t bd = sbase + kk * 4096 + bByteBase + nbswp[p] * 16;
                LDSM_X4_T(bh[p][0], bh[p][1], bh[p][2], bh[p][3], bd + SGBH);
                LDSM_X4_T(bl[p][0], bl[p][1], bl[p][2], bl[p][3], bd + SGBL);
            }
#pragma unroll
            for (int mt = 0; mt < 4; mt++)
#pragma unroll
                for (int nt = 0; nt < 4; nt++) {
                    const unsigned* bph = &bh[nt >> 1][(nt & 1) * 2];
                    const unsigned* bpl = &bl[nt >> 1][(nt & 1) * 2];
                    mma16816(acc[mt][nt], ah[mt], bph);
                    mma16816(acc[mt][nt], al[mt], bph);
                    mma16816(acc[mt][nt], ah[mt], bpl);
                }
        }
    }
#undef G_ISSUE

    __syncthreads();
    const int lr0 = warp_m * 64 + (lane >> 2);       // local row 0..127
    const int lc0 = warp_n * 32 + (lane & 3) * 2;    // local col

    if (mode == 0) {
        const int r0 = bm + lr0;
        const int c0 = bn + lc0;
#pragma unroll
        for (int mt = 0; mt < 4; mt++)
#pragma unroll
            for (int nt = 0; nt < 4; nt++) {
                float* p0 = C + (size_t)(r0 + mt * 16) * N + c0 + nt * 8;
                float* p1 = C + (size_t)(r0 + mt * 16 + 8) * N + c0 + nt * 8;
                *(float2*)p0 = make_float2(acc[mt][nt][0], acc[mt][nt][1]);
                *(float2*)p1 = make_float2(acc[mt][nt][2], acc[mt][nt][3]);
            }
        return;
    }

    // ---- mode 1: fused QKV epilogue; tile = one head of one region ----
    const int region = bn >> 11;            // 0=q 1=k 2=v
    const int head   = (bn & 2047) >> 7;
    __nv_bfloat16* dh = (region == 0) ? g_qh : (region == 1) ? g_kh : g_vh;
    __nv_bfloat16* dl = (region == 0) ? g_ql : (region == 1) ? g_kl : g_vl;

    if (region == 2) {
        // V: no rope — split straight from registers, head-major coalesced enough
#pragma unroll
        for (int mt = 0; mt < 4; mt++) {
#pragma unroll
            for (int rr = 0; rr < 2; rr++) {
                int grow = bm + lr0 + mt * 16 + rr * 8;
                int t = grow & (T_ - 1), b = grow >> 11;
                size_t dst = ((size_t)(b * H_ + head) * T_ + t) * D_ + lc0;
#pragma unroll
                for (int nt = 0; nt < 4; nt++) {
                    unsigned h, l;
                    split2(acc[mt][nt][2 * rr], acc[mt][nt][2 * rr + 1], h, l);
                    *(unsigned*)(dh + dst + nt * 8) = h;
                    *(unsigned*)(dl + dst + nt * 8) = l;
                }
            }
        }
        return;
    }

    // Q/K: stage fp32 tile in smem, rope pairs (j, j+64)
    float* sf = (float*)smem;               // [128][132] = 67584B <= 96KB
#pragma unroll
    for (int mt = 0; mt < 4; mt++)
#pragma unroll
        for (int nt = 0; nt < 4; nt++) {
            int r0l = lr0 + mt * 16;
            *(float2*)&sf[(r0l)     * 132 + lc0 + nt * 8] = make_float2(acc[mt][nt][0], acc[mt][nt][1]);
            *(float2*)&sf[(r0l + 8) * 132 + lc0 + nt * 8] = make_float2(acc[mt][nt][2], acc[mt][nt][3]);
        }
    __syncthreads();

    const float qs = (region == 0) ? 0.088388347648318447f : 1.0f;
#pragma unroll 4
    for (int p = 0; p < 32; p++) {
        int linear = p * 256 + tid;          // 8192 = 128 rows x 64 pairs
        int r = linear >> 6;
        int j = linear & 63;
        float s1 = sf[r * 132 + j];
        float s2 = sf[r * 132 + j + 64];
        int grow = bm + r;
        int t = grow & (T_ - 1), b = grow >> 11;
        float sn = g_sin[t * HALF_ + j];
        float cs = g_cos[t * HALF_ + j];
        float va = (s1 * cs - s2 * sn) * qs;
        float vb = (s2 * cs + s1 * sn) * qs;
        size_t dst = ((size_t)(b * H_ + head) * T_ + t) * D_ + j;
        splitw(va, dh, dl, dst);
        splitw(vb, dh, dl, dst + 64);
    }
}

// =================================================================================
//  Tensor-core causal flash attention (round-7 version: Q frags in regs,
//  cp.async double-buffered KV, epilogue -> bf16 hi/lo)
// =================================================================================
#define FKH 0
#define FKL 16384
#define FVH 32768
#define FVL 49152
#define FSTAGE 65536
#define FSM_TOTAL 131072

__device__ __forceinline__ uint32_t fsw(int r, int c) {
    return (uint32_t)(r * 256 + ((((c ^ r) & 7) | (c & 8)) << 4));
}

__global__ void __launch_bounds__(256, 1) flash_mma_kernel()
{
    extern __shared__ char fsm[];
    const uint32_t sb = (uint32_t)__cvta_generic_to_shared(fsm);

    const int i0  = (gridDim.x - 1) - blockIdx.x;
    const int bh  = blockIdx.y;
    const int tid = threadIdx.x;
    const int lane = tid & 31;
    const int w    = tid >> 5;
    const int quad = lane >> 3;
    const int rq   = lane & 7;
    const int lr   = lane >> 2;
    const int lq   = lane & 3;

    const size_t kvbase   = (size_t)bh * (T_ * D_);
    const size_t qrowbase = kvbase + (size_t)i0 * 128 * D_;

    {
        int r  = tid >> 1;
        int cb = (tid & 1) * 8;
        const size_t g = qrowbase + (size_t)r * D_;
#pragma unroll
        for (int j = 0; j < 8; j++) {
            int c = cb + j;
            uint32_t sw = fsw(r, c);
            *(uint4*)(fsm + sw)         = *(const uint4*)(g_qh + g + c * 8);
            *(uint4*)(fsm + 32768 + sw) = *(const uint4*)(g_ql + g + c * 8);
        }
    }
    __syncthreads();

    const int kvr  = tid >> 2;
    const int kvcb = (tid & 3) * 4;
    const int jmax = 2 * i0 + 1;
#define KV_ISSUE(J, BUF) do { \
    const size_t g_ = kvbase + (size_t)((J) * 64 + kvr) * D_; \
    const uint32_t base_ = sb + (BUF) * FSTAGE; \
    _Pragma("unroll") for (int j_ = 0; j_ < 4; j_++) { \
        int c_ = kvcb + j_; \
        uint32_t sw_ = fsw(kvr, c_); \
        CP16(base_ + FKH + sw_, g_kh + g_ + c_ * 8); \
        CP16(base_ + FKL + sw_, g_kl + g_ + c_ * 8); \
        CP16(base_ + FVH + sw_, g_vh + g_ + c_ * 8); \
        CP16(base_ + FVL + sw_, g_vl + g_ + c_ * 8); } \
    CP_COMMIT(); } while (0)

    KV_ISSUE(0, 1);

    const int arow  = 16 * w + (quad & 1) * 8 + rq;
    const int rB    = (quad & 1) * 8 + rq;
    const int cHalf = quad >> 1;

    unsigned qh[8][4], ql[8][4];
#pragma unroll
    for (int kk = 0; kk < 8; kk++) {
        uint32_t aaddr = sb + fsw(arow, 2 * kk + cHalf);
        LDSM_X4(qh[kk][0], qh[kk][1], qh[kk][2], qh[kk][3], aaddr);
        LDSM_X4(ql[kk][0], ql[kk][1], ql[kk][2], ql[kk][3], aaddr + 32768);
    }

    float o[16][4];
#pragma unroll
    for (int dt = 0; dt < 16; dt++)
#pragma unroll
        for (int e = 0; e < 4; e++) o[dt][e] = 0.f;
    float mcur[2] = {-3.4e38f, -3.4e38f};
    float lcur[2] = {0.f, 0.f};

    int buf = 1;
    for (int j0 = 0; j0 <= jmax; j0++) {
        CP_WAIT0();
        __syncthreads();
        if (j0 < jmax) KV_ISSUE(j0 + 1, buf ^ 1);

        const uint32_t kvb = sb + buf * FSTAGE;

        float s[8][4];
#pragma unroll
        for (int nt = 0; nt < 8; nt++)
#pragma unroll
            for (int e = 0; e < 4; e++) s[nt][e] = 0.f;

#pragma unroll
        for (int kk = 0; kk < 8; kk++) {
            const int ca = 2 * kk + cHalf;
            unsigned kh4[4][4], kl4[4][4];
#pragma unroll
            for (int p = 0; p < 4; p++) {
                uint32_t kaddr = kvb + fsw(16 * p + rB, ca);
                LDSM_X4(kh4[p][0], kh4[p][1], kh4[p][2], kh4[p][3], kaddr + FKH);
                LDSM_X4(kl4[p][0], kl4[p][1], kl4[p][2], kl4[p][3], kaddr + FKL);
            }
#pragma unroll
            for (int p = 0; p < 4; p++) {
                unsigned bh0[2] = {kh4[p][0], kh4[p][2]};
                unsigned bh1[2] = {kh4[p][1], kh4[p][3]};
                unsigned bl0[2] = {kl4[p][0], kl4[p][2]};
                unsigned bl1[2] = {kl4[p][1], kl4[p][3]};
                mma16816(s[2*p],   qh[kk], bh0);
                mma16816(s[2*p],   ql[kk], bh0);
                mma16816(s[2*p],   qh[kk], bl0);
                mma16816(s[2*p+1], qh[kk], bh1);
                mma16816(s[2*p+1], ql[kk], bh1);
                mma16816(s[2*p+1], qh[kk], bl1);
            }
        }

        if (j0 >= 2 * i0) {
            const int qr0 = i0 * 128 + 16 * w + lr;
            const int kc0 = j0 * 64 + 2 * lq;
#pragma unroll
            for (int nt = 0; nt < 8; nt++)
#pragma unroll
                for (int e = 0; e < 4; e++) {
                    int r = qr0 + (e >> 1) * 8;
                    int c = kc0 + 8 * nt + (e & 1);
                    if (c > r) s[nt][e] = -3.4e38f;
                }
        }

#pragma unroll
        for (int z = 0; z < 2; z++) {
            float mx = -3.4e38f;
#pragma unroll
            for (int nt = 0; nt < 8; nt++)
                mx = fmaxf(mx, fmaxf(s[nt][2*z], s[nt][2*z+1]));
            mx = fmaxf(mx, __shfl_xor_sync(0xffffffffu, mx, 1));
            mx = fmaxf(mx, __shfl_xor_sync(0xffffffffu, mx, 2));
            float mn = fmaxf(mcur[z], mx);
            float alpha = fast_exp(mcur[z] - mn);
            float ls = 0.f;
#pragma unroll
            for (int nt = 0; nt < 8; nt++) {
                float p0 = fast_exp(s[nt][2*z]   - mn);
                float p1 = fast_exp(s[nt][2*z+1] - mn);
                s[nt][2*z] = p0; s[nt][2*z+1] = p1;
                ls += p0 + p1;
            }
            ls += __shfl_xor_sync(0xffffffffu, ls, 1);
            ls += __shfl_xor_sync(0xffffffffu, ls, 2);
            lcur[z] = lcur[z] * alpha + ls;
            mcur[z] = mn;
#pragma unroll
            for (int dt = 0; dt < 16; dt++) {
                o[dt][2*z]   *= alpha;
                o[dt][2*z+1] *= alpha;
            }
        }

        unsigned ph[4][4], pl[4][4];
#pragma unroll
        for (int kk2 = 0; kk2 < 4; kk2++) {
            split2(s[2*kk2][0],   s[2*kk2][1],   ph[kk2][0], pl[kk2][0]);
            split2(s[2*kk2][2],   s[2*kk2][3],   ph[kk2][1], pl[kk2][1]);
            split2(s[2*kk2+1][0], s[2*kk2+1][1], ph[kk2][2], pl[kk2][2]);
            split2(s[2*kk2+1][2], s[2*kk2+1][3], ph[kk2][3], pl[kk2][3]);
        }

#pragma unroll
        for (int kk2 = 0; kk2 < 4; kk2++) {
            const int rV = 16 * kk2 + rB;
#pragma unroll
            for (int p = 0; p < 8; p++) {
                unsigned vh4[4], vl4[4];
                uint32_t vaddr = kvb + fsw(rV, 2 * p + cHalf);
                LDSM_X4_T(vh4[0], vh4[1], vh4[2], vh4[3], vaddr + FVH);
                LDSM_X4_T(vl4[0], vl4[1], vl4[2], vl4[3], vaddr + FVL);
                mma16816(o[2*p],   ph[kk2], &vh4[0]);
                mma16816(o[2*p],   pl[kk2], &vh4[0]);
                mma16816(o[2*p],   ph[kk2], &vl4[0]);
                mma16816(o[2*p+1], ph[kk2], &vh4[2]);
                mma16816(o[2*p+1], pl[kk2], &vh4[2]);
                mma16816(o[2*p+1], ph[kk2], &vl4[2]);
            }
        }
        buf ^= 1;
    }
#undef KV_ISSUE

    const float inv0 = 1.f / lcur[0];
    const float inv1 = 1.f / lcur[1];
    const size_t obase = ((size_t)bh * T_ + (size_t)i0 * 128 + 16 * w + lr) * D_;
#pragma unroll
    for (int dt = 0; dt < 16; dt++) {
        int col = 8 * dt + 2 * lq;
        unsigned h0, l0, h1, l1;
        split2(o[dt][0] * inv0, o[dt][1] * inv0, h0, l0);
        split2(o[dt][2] * inv1, o[dt][3] * inv1, h1, l1);
        *(unsigned*)(g_oh + obase + col)          = h0;
        *(unsigned*)(g_ol + obase + col)          = l0;
        *(unsigned*)(g_oh + obase + 8 * D_ + col) = h1;
        *(unsigned*)(g_ol + obase + 8 * D_ + col) = l1;
    }
}

// ---------------- launch ----------------
extern "C" void kernel_launch(void* const* d_in, const int* in_sizes, int n_in,
                              void* d_out, int out_size)
{
    const float* x    = (const float*)d_in[0];
    const float* Wqkv = (const float*)d_in[1];
    const float* Wout = (const float*)d_in[2];
    float* out = (float*)d_out;

    __nv_bfloat16 *xh, *xl, *w1h, *w1l, *w2h, *w2l, *oh, *ol;
    cudaGetSymbolAddress((void**)&xh,  g_xh);
    cudaGetSymbolAddress((void**)&xl,  g_xl);
    cudaGetSymbolAddress((void**)&w1h, g_w1h);
    cudaGetSymbolAddress((void**)&w1l, g_w1l);
    cudaGetSymbolAddress((void**)&w2h, g_w2h);
    cudaGetSymbolAddress((void**)&w2l, g_w2l);
    cudaGetSymbolAddress((void**)&oh,  g_oh);
    cudaGetSymbolAddress((void**)&ol,  g_ol);

    cudaFuncSetAttribute(mma_gemm, cudaFuncAttributeMaxDynamicSharedMemorySize, GSM_TOTAL);
    cudaFuncSetAttribute(flash_mma_kernel, cudaFuncAttributeMaxDynamicSharedMemorySize, FSM_TOTAL);

    // 0) pre-split inputs + rope tables
    split_kernel<<<(M_ * C_ / 4) / 256, 256>>>(x, xh, xl);
    split_kernel<<<((size_t)C_ * N1_ / 4) / 256, 256>>>(Wqkv, w1h, w1l);
    split_kernel<<<((size_t)C_ * C_ / 4) / 256, 256>>>(Wout, w2h, w2l);
    rope_table_kernel<<<(T_ * HALF_ + 255) / 256, 256>>>();
    // 1) QKV projection with fused rope/scale/split/transpose epilogue
    mma_gemm<<<dim3(N1_ / 128, M_ / 128), 256, GSM_TOTAL>>>(xh, xl, w1h, w1l, nullptr, M_, N1_, C_, 1);
    // 2) tensor-core causal flash attention
    flash_mma_kernel<<<dim3(T_ / 128, BH_), 256, FSM_TOTAL>>>();
    // 3) output projection (plain fp32 epilogue)
    mma_gemm<<<dim3(C_ / 128, M_ / 128), 256, GSM_TOTAL>>>(oh, ol, w2h, w2l, out, M_, C_, C_, 0);
}

// round 11
// speedup vs baseline: 1.0496x; 1.0120x over previous
#include <cuda_runtime.h>
#include <cuda_bf16.h>
#include <cstdint>
#include <math.h>

#define B_   2
#define T_   2048
#define C_   2048
#define H_   16
#define D_   128
#define HALF_ 64
#define M_   (B_*T_)       // 4096
#define N1_  (3*C_)        // 6144
#define BH_  (B_*H_)       // 32

// ---------------- scratch (device globals) ----------------
__device__ float g_sin[T_ * HALF_];
__device__ float g_cos[T_ * HALF_];
__device__ __nv_bfloat16 g_qh[(size_t)BH_ * T_ * D_];
__device__ __nv_bfloat16 g_ql[(size_t)BH_ * T_ * D_];
__device__ __nv_bfloat16 g_kh[(size_t)BH_ * T_ * D_];
__device__ __nv_bfloat16 g_kl[(size_t)BH_ * T_ * D_];
__device__ __nv_bfloat16 g_vh[(size_t)BH_ * T_ * D_];
__device__ __nv_bfloat16 g_vl[(size_t)BH_ * T_ * D_];
__device__ __nv_bfloat16 g_xh[(size_t)M_ * C_];
__device__ __nv_bfloat16 g_xl[(size_t)M_ * C_];
__device__ __nv_bfloat16 g_w1h[(size_t)C_ * N1_];
__device__ __nv_bfloat16 g_w1l[(size_t)C_ * N1_];
__device__ __nv_bfloat16 g_w2h[(size_t)C_ * C_];
__device__ __nv_bfloat16 g_w2l[(size_t)C_ * C_];
__device__ __nv_bfloat16 g_oh[(size_t)M_ * C_];
__device__ __nv_bfloat16 g_ol[(size_t)M_ * C_];

// ---------------- fast exp (FFMA-pipe) --------------
__device__ __forceinline__ float fast_exp(float x) {
    x = fmaxf(x, -87.0f);
    float t = x * 1.4426950408889634f;
    int   i = __float2int_rn(t);
    float f = t - (float)i;
    float p =          1.3333558146428443e-3f;
    p = fmaf(p, f, 9.6181291780723730e-3f);
    p = fmaf(p, f, 5.5504108664821580e-2f);
    p = fmaf(p, f, 2.4022650695910072e-1f);
    p = fmaf(p, f, 6.9314718055994531e-1f);
    p = fmaf(p, f, 1.0f);
    return __int_as_float((i + 127) << 23) * p;
}

// ---------------- MMA / LDSM / cp.async primitives ----------------
#define LDSM_X4(R0,R1,R2,R3,ADDR) \
    asm volatile("ldmatrix.sync.aligned.m8n8.x4.shared.b16 {%0,%1,%2,%3}, [%4];" \
                 : "=r"(R0), "=r"(R1), "=r"(R2), "=r"(R3) : "r"(ADDR))
#define LDSM_X4_T(R0,R1,R2,R3,ADDR) \
    asm volatile("ldmatrix.sync.aligned.m8n8.x4.trans.shared.b16 {%0,%1,%2,%3}, [%4];" \
                 : "=r"(R0), "=r"(R1), "=r"(R2), "=r"(R3) : "r"(ADDR))
#define CP16(DST, SRC) \
    asm volatile("cp.async.cg.shared.global [%0], [%1], 16;" :: "r"(DST), "l"(SRC))
#define CP_COMMIT()  asm volatile("cp.async.commit_group;" ::: "memory")
#define CP_WAIT0()   asm volatile("cp.async.wait_group 0;" ::: "memory")
#define CP_WAIT1()   asm volatile("cp.async.wait_group 1;" ::: "memory")

__device__ __forceinline__ void mma16816(float* d, const unsigned* a, const unsigned* b) {
    asm volatile(
        "mma.sync.aligned.m16n8k16.row.col.f32.bf16.bf16.f32 "
        "{%0,%1,%2,%3}, {%4,%5,%6,%7}, {%8,%9}, {%0,%1,%2,%3};"
        : "+f"(d[0]), "+f"(d[1]), "+f"(d[2]), "+f"(d[3])
        : "r"(a[0]), "r"(a[1]), "r"(a[2]), "r"(a[3]), "r"(b[0]), "r"(b[1]));
}

__device__ __forceinline__ void split2(float x, float y, unsigned& hi, unsigned& lo) {
    __nv_bfloat162 h2 = __floats2bfloat162_rn(x, y);
    float hx = __bfloat162float(h2.x);
    float hy = __bfloat162float(h2.y);
    __nv_bfloat162 l2 = __floats2bfloat162_rn(x - hx, y - hy);
    hi = *reinterpret_cast<unsigned*>(&h2);
    lo = *reinterpret_cast<unsigned*>(&l2);
}

__device__ __forceinline__ void splitw(float x, __nv_bfloat16* hi, __nv_bfloat16* lo, size_t i) {
    __nv_bfloat16 h = __float2bfloat16(x);
    hi[i] = h;
    lo[i] = __float2bfloat16(x - __bfloat162float(h));
}

// =================================================================================
//  merged prep kernel: rope-table blocks first (FP64-bound), then the three
//  fp32->bf16 hi/lo split regions (DRAM-bound) — heterogeneous blocks co-reside.
// =================================================================================
#define PB_ROPE 512                          // T*HALF/256
#define PB_X    (M_ * C_ / 4 / 256)          // 8192
#define PB_W1   ((size_t)C_ * N1_ / 4 / 256) // 12288
#define PB_W2   ((size_t)C_ * C_ / 4 / 256)  // 4096
#define PB_TOTAL (PB_ROPE + PB_X + PB_W1 + PB_W2)

__device__ __forceinline__ void split_body(const float* __restrict__ src,
                                           __nv_bfloat16* __restrict__ th,
                                           __nv_bfloat16* __restrict__ tl, size_t blk)
{
    size_t i = (blk * 256 + threadIdx.x) * 4;
    float4 v = *(const float4*)(src + i);
    unsigned h0, l0, h1, l1;
    split2(v.x, v.y, h0, l0);
    split2(v.z, v.w, h1, l1);
    *(uint2*)(th + i) = make_uint2(h0, h1);
    *(uint2*)(tl + i) = make_uint2(l0, l1);
}

__global__ void prep_kernel(const float* __restrict__ x,
                            const float* __restrict__ Wqkv,
                            const float* __restrict__ Wout)
{
    size_t blk = blockIdx.x;
    if (blk < PB_ROPE) {
        int idx = (int)blk * 256 + threadIdx.x;
        int t = idx / HALF_, j = idx % HALF_;
        double div  = exp(-(double)(2 * j) * 9.210340371976184 / 128.0);
        float  divf = (float)div;
        float  angf = (float)t * divf;
        g_sin[idx] = (float)sin((double)angf);
        g_cos[idx] = (float)cos((double)angf);
        return;
    }
    blk -= PB_ROPE;
    if (blk < PB_X)  { split_body(x,    g_xh,  g_xl,  blk); return; }
    blk -= PB_X;
    if (blk < PB_W1) { split_body(Wqkv, g_w1h, g_w1l, blk); return; }
    blk -= PB_W1;
    split_body(Wout, g_w2h, g_w2l, blk);
}

// =================================================================================
//  bf16x3 split-precision tensor-core GEMM (cp.async 3-stage, BK=32, 2 CTAs/SM).
//  mode 0: plain fp32 C epilogue (GEMM2).
//  mode 1: fused QKV epilogue (RoPE + scale + split, head-major).
// =================================================================================
#define SGBH  16384
#define SGBL  24576
#define STAGE_ 32768
#define NSTAGE 3
#define GSM_TOTAL (NSTAGE * STAGE_)   // 98304

__global__ void __launch_bounds__(256, 2) mma_gemm(const __nv_bfloat16* __restrict__ Ah,
                                                   const __nv_bfloat16* __restrict__ Al,
                                                   const __nv_bfloat16* __restrict__ Bh,
                                                   const __nv_bfloat16* __restrict__ Bl,
                                                   float* __restrict__ C,
                                                   int M, int N, int K, int mode)
{
    extern __shared__ char smem[];
    const uint32_t smem_u32 = (uint32_t)__cvta_generic_to_shared(smem);

    const int tid  = threadIdx.x;
    const int lane = tid & 31;
    const int wid  = tid >> 5;
    const int warp_m = wid & 1;
    const int warp_n = wid >> 1;
    const int quad = lane >> 3;
    const int rq   = lane & 7;

    const int bm = blockIdx.y * 128;
    const int bn = blockIdx.x * 128;

    uint32_t swA[4], swB[4];
    const __nv_bfloat16* pA[4];
    const __nv_bfloat16* pB[4];
#pragma unroll
    for (int i = 0; i < 4; i++) {
        int ia = i * 256 + tid;
        int ra = ia >> 3, ca = ia & 7;
        swA[i] = ra * 128 + ((ca ^ (ra & 7)) << 4);
        pA[i]  = (ca < 4 ? Ah : Al) + (size_t)(bm + ra) * K + (ca & 3) * 8;
        int hilo = ia >> 9;
        int rem  = ia & 511;
        int rb = rem >> 4, cb = rem & 15;
        swB[i] = (hilo ? SGBL : SGBH) + rb * 256 + (((cb & 8) | ((cb & 7) ^ (rb & 7))) << 4);
        pB[i]  = (hilo ? Bl : Bh) + (size_t)rb * N + bn + cb * 8;
    }

    const int aRowL = warp_m * 64 + (quad & 1) * 8 + rq;
    const int kHalf = quad >> 1;
    const int arow7 = aRowL & 7;
    const int arowByte = aRowL * 128;

    const int kL = (quad & 1) * 8 + rq;
    int nbswp[2];
#pragma unroll
    for (int p = 0; p < 2; p++) {
        int nb = warp_n * 4 + (quad >> 1) + p * 2;
        nbswp[p] = (nb & 8) | ((nb & 7) ^ (kL & 7));
    }
    const int bByteBase = kL * 256;

    float acc[4][4][4];
#pragma unroll
    for (int mt = 0; mt < 4; mt++)
#pragma unroll
        for (int nt = 0; nt < 4; nt++)
#pragma unroll
            for (int c = 0; c < 4; c++) acc[mt][nt][c] = 0.f;

#define G_ISSUE(k0, buf) do { \
    const uint32_t b_ = smem_u32 + (buf) * STAGE_; \
    _Pragma("unroll") for (int i = 0; i < 4; i++) { \
        CP16(b_ + swA[i], pA[i] + (k0)); \
        CP16(b_ + swB[i], pB[i] + (size_t)(k0) * N); } \
    CP_COMMIT(); } while (0)

    const int KT = K >> 5;
    G_ISSUE(0, 0);
    G_ISSUE(32, 1);

    for (int kt = 0; kt < KT; kt++) {
        if (kt + 1 < KT) { CP_WAIT1(); } else { CP_WAIT0(); }
        __syncthreads();
        if (kt + 2 < KT) G_ISSUE((kt + 2) * 32, (kt + 2) % NSTAGE);

        const uint32_t sbase = smem_u32 + (kt % NSTAGE) * STAGE_;
#pragma unroll
        for (int kk = 0; kk < 2; kk++) {
            unsigned ah[4][4], al[4][4], bh[2][4], bl[2][4];
            const int chi = 2 * kk + kHalf;
            const int asw_h = ((chi)     ^ arow7) << 4;
            const int asw_l = ((chi + 4) ^ arow7) << 4;
#pragma unroll
            for (int mt = 0; mt < 4; mt++) {
                uint32_t ad = sbase + arowByte + mt * 2048;
                LDSM_X4(ah[mt][0], ah[mt][1], ah[mt][2], ah[mt][3], ad + asw_h);
                LDSM_X4(al[mt][0], al[mt][1], al[mt][2], al[mt][3], ad + asw_l);
            }
#pragma unroll
            for (int p = 0; p < 2; p++) {
                uint32_t bd = sbase + kk * 4096 + bByteBase + nbswp[p] * 16;
                LDSM_X4_T(bh[p][0], bh[p][1], bh[p][2], bh[p][3], bd + SGBH);
                LDSM_X4_T(bl[p][0], bl[p][1], bl[p][2], bl[p][3], bd + SGBL);
            }
#pragma unroll
            for (int mt = 0; mt < 4; mt++)
#pragma unroll
                for (int nt = 0; nt < 4; nt++) {
                    const unsigned* bph = &bh[nt >> 1][(nt & 1) * 2];
                    const unsigned* bpl = &bl[nt >> 1][(nt & 1) * 2];
                    mma16816(acc[mt][nt], ah[mt], bph);
                    mma16816(acc[mt][nt], al[mt], bph);
                    mma16816(acc[mt][nt], ah[mt], bpl);
                }
        }
    }
#undef G_ISSUE

    __syncthreads();
    const int lr0 = warp_m * 64 + (lane >> 2);
    const int lc0 = warp_n * 32 + (lane & 3) * 2;

    if (mode == 0) {
        const int r0 = bm + lr0;
        const int c0 = bn + lc0;
#pragma unroll
        for (int mt = 0; mt < 4; mt++)
#pragma unroll
            for (int nt = 0; nt < 4; nt++) {
                float* p0 = C + (size_t)(r0 + mt * 16) * N + c0 + nt * 8;
                float* p1 = C + (size_t)(r0 + mt * 16 + 8) * N + c0 + nt * 8;
                *(float2*)p0 = make_float2(acc[mt][nt][0], acc[mt][nt][1]);
                *(float2*)p1 = make_float2(acc[mt][nt][2], acc[mt][nt][3]);
            }
        return;
    }

    // ---- mode 1: fused QKV epilogue; tile = one head of one region ----
    const int region = bn >> 11;            // 0=q 1=k 2=v
    const int head   = (bn & 2047) >> 7;
    __nv_bfloat16* dh = (region == 0) ? g_qh : (region == 1) ? g_kh : g_vh;
    __nv_bfloat16* dl = (region == 0) ? g_ql : (region == 1) ? g_kl : g_vl;

    if (region == 2) {
#pragma unroll
        for (int mt = 0; mt < 4; mt++) {
#pragma unroll
            for (int rr = 0; rr < 2; rr++) {
                int grow = bm + lr0 + mt * 16 + rr * 8;
                int t = grow & (T_ - 1), b = grow >> 11;
                size_t dst = ((size_t)(b * H_ + head) * T_ + t) * D_ + lc0;
#pragma unroll
                for (int nt = 0; nt < 4; nt++) {
                    unsigned h, l;
                    split2(acc[mt][nt][2 * rr], acc[mt][nt][2 * rr + 1], h, l);
                    *(unsigned*)(dh + dst + nt * 8) = h;
                    *(unsigned*)(dl + dst + nt * 8) = l;
                }
            }
        }
        return;
    }

    float* sf = (float*)smem;
#pragma unroll
    for (int mt = 0; mt < 4; mt++)
#pragma unroll
        for (int nt = 0; nt < 4; nt++) {
            int r0l = lr0 + mt * 16;
            *(float2*)&sf[(r0l)     * 132 + lc0 + nt * 8] = make_float2(acc[mt][nt][0], acc[mt][nt][1]);
            *(float2*)&sf[(r0l + 8) * 132 + lc0 + nt * 8] = make_float2(acc[mt][nt][2], acc[mt][nt][3]);
        }
    __syncthreads();

    const float qs = (region == 0) ? 0.088388347648318447f : 1.0f;
#pragma unroll 4
    for (int p = 0; p < 32; p++) {
        int linear = p * 256 + tid;
        int r = linear >> 6;
        int j = linear & 63;
        float s1 = sf[r * 132 + j];
        float s2 = sf[r * 132 + j + 64];
        int grow = bm + r;
        int t = grow & (T_ - 1), b = grow >> 11;
        float sn = g_sin[t * HALF_ + j];
        float cs = g_cos[t * HALF_ + j];
        float va = (s1 * cs - s2 * sn) * qs;
        float vb = (s2 * cs + s1 * sn) * qs;
        size_t dst = ((size_t)(b * H_ + head) * T_ + t) * D_ + j;
        splitw(va, dh, dl, dst);
        splitw(vb, dh, dl, dst + 64);
    }
}

// =================================================================================
//  Tensor-core causal flash attention (round-7 version)
// =================================================================================
#define FKH 0
#define FKL 16384
#define FVH 32768
#define FVL 49152
#define FSTAGE 65536
#define FSM_TOTAL 131072

__device__ __forceinline__ uint32_t fsw(int r, int c) {
    return (uint32_t)(r * 256 + ((((c ^ r) & 7) | (c & 8)) << 4));
}

__global__ void __launch_bounds__(256, 1) flash_mma_kernel()
{
    extern __shared__ char fsm[];
    const uint32_t sb = (uint32_t)__cvta_generic_to_shared(fsm);

    const int i0  = (gridDim.x - 1) - blockIdx.x;
    const int bh  = blockIdx.y;
    const int tid = threadIdx.x;
    const int lane = tid & 31;
    const int w    = tid >> 5;
    const int quad = lane >> 3;
    const int rq   = lane & 7;
    const int lr   = lane >> 2;
    const int lq   = lane & 3;

    const size_t kvbase   = (size_t)bh * (T_ * D_);
    const size_t qrowbase = kvbase + (size_t)i0 * 128 * D_;

    {
        int r  = tid >> 1;
        int cb = (tid & 1) * 8;
        const size_t g = qrowbase + (size_t)r * D_;
#pragma unroll
        for (int j = 0; j < 8; j++) {
            int c = cb + j;
            uint32_t sw = fsw(r, c);
            *(uint4*)(fsm + sw)         = *(const uint4*)(g_qh + g + c * 8);
            *(uint4*)(fsm + 32768 + sw) = *(const uint4*)(g_ql + g + c * 8);
        }
    }
    __syncthreads();

    const int kvr  = tid >> 2;
    const int kvcb = (tid & 3) * 4;
    const int jmax = 2 * i0 + 1;
#define KV_ISSUE(J, BUF) do { \
    const size_t g_ = kvbase + (size_t)((J) * 64 + kvr) * D_; \
    const uint32_t base_ = sb + (BUF) * FSTAGE; \
    _Pragma("unroll") for (int j_ = 0; j_ < 4; j_++) { \
        int c_ = kvcb + j_; \
        uint32_t sw_ = fsw(kvr, c_); \
        CP16(base_ + FKH + sw_, g_kh + g_ + c_ * 8); \
        CP16(base_ + FKL + sw_, g_kl + g_ + c_ * 8); \
        CP16(base_ + FVH + sw_, g_vh + g_ + c_ * 8); \
        CP16(base_ + FVL + sw_, g_vl + g_ + c_ * 8); } \
    CP_COMMIT(); } while (0)

    KV_ISSUE(0, 1);

    const int arow  = 16 * w + (quad & 1) * 8 + rq;
    const int rB    = (quad & 1) * 8 + rq;
    const int cHalf = quad >> 1;

    unsigned qh[8][4], ql[8][4];
#pragma unroll
    for (int kk = 0; kk < 8; kk++) {
        uint32_t aaddr = sb + fsw(arow, 2 * kk + cHalf);
        LDSM_X4(qh[kk][0], qh[kk][1], qh[kk][2], qh[kk][3], aaddr);
        LDSM_X4(ql[kk][0], ql[kk][1], ql[kk][2], ql[kk][3], aaddr + 32768);
    }

    float o[16][4];
#pragma unroll
    for (int dt = 0; dt < 16; dt++)
#pragma unroll
        for (int e = 0; e < 4; e++) o[dt][e] = 0.f;
    float mcur[2] = {-3.4e38f, -3.4e38f};
    float lcur[2] = {0.f, 0.f};

    int buf = 1;
    for (int j0 = 0; j0 <= jmax; j0++) {
        CP_WAIT0();
        __syncthreads();
        if (j0 < jmax) KV_ISSUE(j0 + 1, buf ^ 1);

        const uint32_t kvb = sb + buf * FSTAGE;

        float s[8][4];
#pragma unroll
        for (int nt = 0; nt < 8; nt++)
#pragma unroll
            for (int e = 0; e < 4; e++) s[nt][e] = 0.f;

#pragma unroll
        for (int kk = 0; kk < 8; kk++) {
            const int ca = 2 * kk + cHalf;
            unsigned kh4[4][4], kl4[4][4];
#pragma unroll
            for (int p = 0; p < 4; p++) {
                uint32_t kaddr = kvb + fsw(16 * p + rB, ca);
                LDSM_X4(kh4[p][0], kh4[p][1], kh4[p][2], kh4[p][3], kaddr + FKH);
                LDSM_X4(kl4[p][0], kl4[p][1], kl4[p][2], kl4[p][3], kaddr + FKL);
            }
#pragma unroll
            for (int p = 0; p < 4; p++) {
                unsigned bh0[2] = {kh4[p][0], kh4[p][2]};
                unsigned bh1[2] = {kh4[p][1], kh4[p][3]};
                unsigned bl0[2] = {kl4[p][0], kl4[p][2]};
                unsigned bl1[2] = {kl4[p][1], kl4[p][3]};
                mma16816(s[2*p],   qh[kk], bh0);
                mma16816(s[2*p],   ql[kk], bh0);
                mma16816(s[2*p],   qh[kk], bl0);
                mma16816(s[2*p+1], qh[kk], bh1);
                mma16816(s[2*p+1], ql[kk], bh1);
                mma16816(s[2*p+1], qh[kk], bl1);
            }
        }

        if (j0 >= 2 * i0) {
            const int qr0 = i0 * 128 + 16 * w + lr;
            const int kc0 = j0 * 64 + 2 * lq;
#pragma unroll
            for (int nt = 0; nt < 8; nt++)
#pragma unroll
                for (int e = 0; e < 4; e++) {
                    int r = qr0 + (e >> 1) * 8;
                    int c = kc0 + 8 * nt + (e & 1);
                    if (c > r) s[nt][e] = -3.4e38f;
                }
        }

#pragma unroll
        for (int z = 0; z < 2; z++) {
            float mx = -3.4e38f;
#pragma unroll
            for (int nt = 0; nt < 8; nt++)
                mx = fmaxf(mx, fmaxf(s[nt][2*z], s[nt][2*z+1]));
            mx = fmaxf(mx, __shfl_xor_sync(0xffffffffu, mx, 1));
            mx = fmaxf(mx, __shfl_xor_sync(0xffffffffu, mx, 2));
            float mn = fmaxf(mcur[z], mx);
            float alpha = fast_exp(mcur[z] - mn);
            float ls = 0.f;
#pragma unroll
            for (int nt = 0; nt < 8; nt++) {
                float p0 = fast_exp(s[nt][2*z]   - mn);
                float p1 = fast_exp(s[nt][2*z+1] - mn);
                s[nt][2*z] = p0; s[nt][2*z+1] = p1;
                ls += p0 + p1;
            }
            ls += __shfl_xor_sync(0xffffffffu, ls, 1);
            ls += __shfl_xor_sync(0xffffffffu, ls, 2);
            lcur[z] = lcur[z] * alpha + ls;
            mcur[z] = mn;
#pragma unroll
            for (int dt = 0; dt < 16; dt++) {
                o[dt][2*z]   *= alpha;
                o[dt][2*z+1] *= alpha;
            }
        }

        unsigned ph[4][4], pl[4][4];
#pragma unroll
        for (int kk2 = 0; kk2 < 4; kk2++) {
            split2(s[2*kk2][0],   s[2*kk2][1],   ph[kk2][0], pl[kk2][0]);
            split2(s[2*kk2][2],   s[2*kk2][3],   ph[kk2][1], pl[kk2][1]);
            split2(s[2*kk2+1][0], s[2*kk2+1][1], ph[kk2][2], pl[kk2][2]);
            split2(s[2*kk2+1][2], s[2*kk2+1][3], ph[kk2][3], pl[kk2][3]);
        }

#pragma unroll
        for (int kk2 = 0; kk2 < 4; kk2++) {
            const int rV = 16 * kk2 + rB;
#pragma unroll
            for (int p = 0; p < 8; p++) {
                unsigned vh4[4], vl4[4];
                uint32_t vaddr = kvb + fsw(rV, 2 * p + cHalf);
                LDSM_X4_T(vh4[0], vh4[1], vh4[2], vh4[3], vaddr + FVH);
                LDSM_X4_T(vl4[0], vl4[1], vl4[2], vl4[3], vaddr + FVL);
                mma16816(o[2*p],   ph[kk2], &vh4[0]);
                mma16816(o[2*p],   pl[kk2], &vh4[0]);
                mma16816(o[2*p],   ph[kk2], &vl4[0]);
                mma16816(o[2*p+1], ph[kk2], &vh4[2]);
                mma16816(o[2*p+1], pl[kk2], &vh4[2]);
                mma16816(o[2*p+1], ph[kk2], &vl4[2]);
            }
        }
        buf ^= 1;
    }
#undef KV_ISSUE

    const float inv0 = 1.f / lcur[0];
    const float inv1 = 1.f / lcur[1];
    const size_t obase = ((size_t)bh * T_ + (size_t)i0 * 128 + 16 * w + lr) * D_;
#pragma unroll
    for (int dt = 0; dt < 16; dt++) {
        int col = 8 * dt + 2 * lq;
        unsigned h0, l0, h1, l1;
        split2(o[dt][0] * inv0, o[dt][1] * inv0, h0, l0);
        split2(o[dt][2] * inv1, o[dt][3] * inv1, h1, l1);
        *(unsigned*)(g_oh + obase + col)          = h0;
        *(unsigned*)(g_ol + obase + col)          = l0;
        *(unsigned*)(g_oh + obase + 8 * D_ + col) = h1;
        *(unsigned*)(g_ol + obase + 8 * D_ + col) = l1;
    }
}

// ---------------- launch ----------------
extern "C" void kernel_launch(void* const* d_in, const int* in_sizes, int n_in,
                              void* d_out, int out_size)
{
    const float* x    = (const float*)d_in[0];
    const float* Wqkv = (const float*)d_in[1];
    const float* Wout = (const float*)d_in[2];
    float* out = (float*)d_out;

    __nv_bfloat16 *xh, *xl, *w1h, *w1l, *w2h, *w2l, *oh, *ol;
    cudaGetSymbolAddress((void**)&xh,  g_xh);
    cudaGetSymbolAddress((void**)&xl,  g_xl);
    cudaGetSymbolAddress((void**)&w1h, g_w1h);
    cudaGetSymbolAddress((void**)&w1l, g_w1l);
    cudaGetSymbolAddress((void**)&w2h, g_w2h);
    cudaGetSymbolAddress((void**)&w2l, g_w2l);
    cudaGetSymbolAddress((void**)&oh,  g_oh);
    cudaGetSymbolAddress((void**)&ol,  g_ol);

    cudaFuncSetAttribute(mma_gemm, cudaFuncAttributeMaxDynamicSharedMemorySize, GSM_TOTAL);
    cudaFuncSetAttribute(flash_mma_kernel, cudaFuncAttributeMaxDynamicSharedMemorySize, FSM_TOTAL);

    // 0) merged prep: rope table (fp64 blocks first) + all bf16 hi/lo splits
    prep_kernel<<<(unsigned)PB_TOTAL, 256>>>(x, Wqkv, Wout);
    // 1) QKV projection with fused rope/scale/split/transpose epilogue
    mma_gemm<<<dim3(N1_ / 128, M_ / 128), 256, GSM_TOTAL>>>(xh, xl, w1h, w1l, nullptr, M_, N1_, C_, 1);
    // 2) tensor-core causal flash attention
    flash_mma_kernel<<<dim3(T_ / 128, BH_), 256, FSM_TOTAL>>>();
    // 3) output projection (plain fp32 epilogue)
    mma_gemm<<<dim3(C_ / 128, M_ / 128), 256, GSM_TOTAL>>>(oh, ol, w2h, w2l, out, M_, C_, C_, 0);
}

// round 12
// speedup vs baseline: 1.0510x; 1.0014x over previous
#include <cuda_runtime.h>
#include <cuda_bf16.h>
#include <cstdint>
#include <math.h>

#define B_   2
#define T_   2048
#define C_   2048
#define H_   16
#define D_   128
#define HALF_ 64
#define M_   (B_*T_)       // 4096
#define N1_  (3*C_)        // 6144
#define BH_  (B_*H_)       // 32

// ---------------- scratch (device globals) ----------------
__device__ float g_sin[T_ * HALF_];
__device__ float g_cos[T_ * HALF_];
__device__ __nv_bfloat16 g_qh[(size_t)BH_ * T_ * D_];
__device__ __nv_bfloat16 g_ql[(size_t)BH_ * T_ * D_];
__device__ __nv_bfloat16 g_kh[(size_t)BH_ * T_ * D_];
__device__ __nv_bfloat16 g_kl[(size_t)BH_ * T_ * D_];
__device__ __nv_bfloat16 g_vh[(size_t)BH_ * T_ * D_];
__device__ __nv_bfloat16 g_vl[(size_t)BH_ * T_ * D_];
__device__ __nv_bfloat16 g_xh[(size_t)M_ * C_];
__device__ __nv_bfloat16 g_xl[(size_t)M_ * C_];
__device__ __nv_bfloat16 g_w1h[(size_t)C_ * N1_];
__device__ __nv_bfloat16 g_w1l[(size_t)C_ * N1_];
__device__ __nv_bfloat16 g_w2h[(size_t)C_ * C_];
__device__ __nv_bfloat16 g_w2l[(size_t)C_ * C_];
__device__ __nv_bfloat16 g_oh[(size_t)M_ * C_];
__device__ __nv_bfloat16 g_ol[(size_t)M_ * C_];

// ---------------- fast exp (FFMA-pipe) --------------
__device__ __forceinline__ float fast_exp(float x) {
    x = fmaxf(x, -87.0f);
    float t = x * 1.4426950408889634f;
    int   i = __float2int_rn(t);
    float f = t - (float)i;
    float p =          1.3333558146428443e-3f;
    p = fmaf(p, f, 9.6181291780723730e-3f);
    p = fmaf(p, f, 5.5504108664821580e-2f);
    p = fmaf(p, f, 2.4022650695910072e-1f);
    p = fmaf(p, f, 6.9314718055994531e-1f);
    p = fmaf(p, f, 1.0f);
    return __int_as_float((i + 127) << 23) * p;
}

// ---------------- MMA / LDSM / cp.async primitives ----------------
#define LDSM_X4(R0,R1,R2,R3,ADDR) \
    asm volatile("ldmatrix.sync.aligned.m8n8.x4.shared.b16 {%0,%1,%2,%3}, [%4];" \
                 : "=r"(R0), "=r"(R1), "=r"(R2), "=r"(R3) : "r"(ADDR))
#define LDSM_X4_T(R0,R1,R2,R3,ADDR) \
    asm volatile("ldmatrix.sync.aligned.m8n8.x4.trans.shared.b16 {%0,%1,%2,%3}, [%4];" \
                 : "=r"(R0), "=r"(R1), "=r"(R2), "=r"(R3) : "r"(ADDR))
#define CP16(DST, SRC) \
    asm volatile("cp.async.cg.shared.global [%0], [%1], 16;" :: "r"(DST), "l"(SRC))
#define CP_COMMIT()  asm volatile("cp.async.commit_group;" ::: "memory")
#define CP_WAIT0()   asm volatile("cp.async.wait_group 0;" ::: "memory")
#define CP_WAIT1()   asm volatile("cp.async.wait_group 1;" ::: "memory")

__device__ __forceinline__ void mma16816(float* d, const unsigned* a, const unsigned* b) {
    asm volatile(
        "mma.sync.aligned.m16n8k16.row.col.f32.bf16.bf16.f32 "
        "{%0,%1,%2,%3}, {%4,%5,%6,%7}, {%8,%9}, {%0,%1,%2,%3};"
        : "+f"(d[0]), "+f"(d[1]), "+f"(d[2]), "+f"(d[3])
        : "r"(a[0]), "r"(a[1]), "r"(a[2]), "r"(a[3]), "r"(b[0]), "r"(b[1]));
}

__device__ __forceinline__ void split2(float x, float y, unsigned& hi, unsigned& lo) {
    __nv_bfloat162 h2 = __floats2bfloat162_rn(x, y);
    float hx = __bfloat162float(h2.x);
    float hy = __bfloat162float(h2.y);
    __nv_bfloat162 l2 = __floats2bfloat162_rn(x - hx, y - hy);
    hi = *reinterpret_cast<unsigned*>(&h2);
    lo = *reinterpret_cast<unsigned*>(&l2);
}

__device__ __forceinline__ void splitw(float x, __nv_bfloat16* hi, __nv_bfloat16* lo, size_t i) {
    __nv_bfloat16 h = __float2bfloat16(x);
    hi[i] = h;
    lo[i] = __float2bfloat16(x - __bfloat162float(h));
}

// =================================================================================
//  merged prep kernel (round-11): rope-table blocks first, then the three splits
// =================================================================================
#define PB_ROPE 512
#define PB_X    (M_ * C_ / 4 / 256)
#define PB_W1   ((size_t)C_ * N1_ / 4 / 256)
#define PB_W2   ((size_t)C_ * C_ / 4 / 256)
#define PB_TOTAL (PB_ROPE + PB_X + PB_W1 + PB_W2)

__device__ __forceinline__ void split_body(const float* __restrict__ src,
                                           __nv_bfloat16* __restrict__ th,
                                           __nv_bfloat16* __restrict__ tl, size_t blk)
{
    size_t i = (blk * 256 + threadIdx.x) * 4;
    float4 v = *(const float4*)(src + i);
    unsigned h0, l0, h1, l1;
    split2(v.x, v.y, h0, l0);
    split2(v.z, v.w, h1, l1);
    *(uint2*)(th + i) = make_uint2(h0, h1);
    *(uint2*)(tl + i) = make_uint2(l0, l1);
}

__global__ void prep_kernel(const float* __restrict__ x,
                            const float* __restrict__ Wqkv,
                            const float* __restrict__ Wout)
{
    size_t blk = blockIdx.x;
    if (blk < PB_ROPE) {
        int idx = (int)blk * 256 + threadIdx.x;
        int t = idx / HALF_, j = idx % HALF_;
        double div  = exp(-(double)(2 * j) * 9.210340371976184 / 128.0);
        float  divf = (float)div;
        float  angf = (float)t * divf;
        g_sin[idx] = (float)sin((double)angf);
        g_cos[idx] = (float)cos((double)angf);
        return;
    }
    blk -= PB_ROPE;
    if (blk < PB_X)  { split_body(x,    g_xh,  g_xl,  blk); return; }
    blk -= PB_X;
    if (blk < PB_W1) { split_body(Wqkv, g_w1h, g_w1l, blk); return; }
    blk -= PB_W1;
    split_body(Wout, g_w2h, g_w2l, blk);
}

// =================================================================================
//  bf16x3 split-precision tensor-core GEMM (round-11 version, unchanged)
// =================================================================================
#define SGBH  16384
#define SGBL  24576
#define STAGE_ 32768
#define NSTAGE 3
#define GSM_TOTAL (NSTAGE * STAGE_)

__global__ void __launch_bounds__(256, 2) mma_gemm(const __nv_bfloat16* __restrict__ Ah,
                                                   const __nv_bfloat16* __restrict__ Al,
                                                   const __nv_bfloat16* __restrict__ Bh,
                                                   const __nv_bfloat16* __restrict__ Bl,
                                                   float* __restrict__ C,
                                                   int M, int N, int K, int mode)
{
    extern __shared__ char smem[];
    const uint32_t smem_u32 = (uint32_t)__cvta_generic_to_shared(smem);

    const int tid  = threadIdx.x;
    const int lane = tid & 31;
    const int wid  = tid >> 5;
    const int warp_m = wid & 1;
    const int warp_n = wid >> 1;
    const int quad = lane >> 3;
    const int rq   = lane & 7;

    const int bm = blockIdx.y * 128;
    const int bn = blockIdx.x * 128;

    uint32_t swA[4], swB[4];
    const __nv_bfloat16* pA[4];
    const __nv_bfloat16* pB[4];
#pragma unroll
    for (int i = 0; i < 4; i++) {
        int ia = i * 256 + tid;
        int ra = ia >> 3, ca = ia & 7;
        swA[i] = ra * 128 + ((ca ^ (ra & 7)) << 4);
        pA[i]  = (ca < 4 ? Ah : Al) + (size_t)(bm + ra) * K + (ca & 3) * 8;
        int hilo = ia >> 9;
        int rem  = ia & 511;
        int rb = rem >> 4, cb = rem & 15;
        swB[i] = (hilo ? SGBL : SGBH) + rb * 256 + (((cb & 8) | ((cb & 7) ^ (rb & 7))) << 4);
        pB[i]  = (hilo ? Bl : Bh) + (size_t)rb * N + bn + cb * 8;
    }

    const int aRowL = warp_m * 64 + (quad & 1) * 8 + rq;
    const int kHalf = quad >> 1;
    const int arow7 = aRowL & 7;
    const int arowByte = aRowL * 128;

    const int kL = (quad & 1) * 8 + rq;
    int nbswp[2];
#pragma unroll
    for (int p = 0; p < 2; p++) {
        int nb = warp_n * 4 + (quad >> 1) + p * 2;
        nbswp[p] = (nb & 8) | ((nb & 7) ^ (kL & 7));
    }
    const int bByteBase = kL * 256;

    float acc[4][4][4];
#pragma unroll
    for (int mt = 0; mt < 4; mt++)
#pragma unroll
        for (int nt = 0; nt < 4; nt++)
#pragma unroll
            for (int c = 0; c < 4; c++) acc[mt][nt][c] = 0.f;

#define G_ISSUE(k0, buf) do { \
    const uint32_t b_ = smem_u32 + (buf) * STAGE_; \
    _Pragma("unroll") for (int i = 0; i < 4; i++) { \
        CP16(b_ + swA[i], pA[i] + (k0)); \
        CP16(b_ + swB[i], pB[i] + (size_t)(k0) * N); } \
    CP_COMMIT(); } while (0)

    const int KT = K >> 5;
    G_ISSUE(0, 0);
    G_ISSUE(32, 1);

    for (int kt = 0; kt < KT; kt++) {
        if (kt + 1 < KT) { CP_WAIT1(); } else { CP_WAIT0(); }
        __syncthreads();
        if (kt + 2 < KT) G_ISSUE((kt + 2) * 32, (kt + 2) % NSTAGE);

        const uint32_t sbase = smem_u32 + (kt % NSTAGE) * STAGE_;
#pragma unroll
        for (int kk = 0; kk < 2; kk++) {
            unsigned ah[4][4], al[4][4], bh[2][4], bl[2][4];
            const int chi = 2 * kk + kHalf;
            const int asw_h = ((chi)     ^ arow7) << 4;
            const int asw_l = ((chi + 4) ^ arow7) << 4;
#pragma unroll
            for (int mt = 0; mt < 4; mt++) {
                uint32_t ad = sbase + arowByte + mt * 2048;
                LDSM_X4(ah[mt][0], ah[mt][1], ah[mt][2], ah[mt][3], ad + asw_h);
                LDSM_X4(al[mt][0], al[mt][1], al[mt][2], al[mt][3], ad + asw_l);
            }
#pragma unroll
            for (int p = 0; p < 2; p++) {
                uint32_t bd = sbase + kk * 4096 + bByteBase + nbswp[p] * 16;
                LDSM_X4_T(bh[p][0], bh[p][1], bh[p][2], bh[p][3], bd + SGBH);
                LDSM_X4_T(bl[p][0], bl[p][1], bl[p][2], bl[p][3], bd + SGBL);
            }
#pragma unroll
            for (int mt = 0; mt < 4; mt++)
#pragma unroll
                for (int nt = 0; nt < 4; nt++) {
                    const unsigned* bph = &bh[nt >> 1][(nt & 1) * 2];
                    const unsigned* bpl = &bl[nt >> 1][(nt & 1) * 2];
                    mma16816(acc[mt][nt], ah[mt], bph);
                    mma16816(acc[mt][nt], al[mt], bph);
                    mma16816(acc[mt][nt], ah[mt], bpl);
                }
        }
    }
#undef G_ISSUE

    __syncthreads();
    const int lr0 = warp_m * 64 + (lane >> 2);
    const int lc0 = warp_n * 32 + (lane & 3) * 2;

    if (mode == 0) {
        const int r0 = bm + lr0;
        const int c0 = bn + lc0;
#pragma unroll
        for (int mt = 0; mt < 4; mt++)
#pragma unroll
            for (int nt = 0; nt < 4; nt++) {
                float* p0 = C + (size_t)(r0 + mt * 16) * N + c0 + nt * 8;
                float* p1 = C + (size_t)(r0 + mt * 16 + 8) * N + c0 + nt * 8;
                *(float2*)p0 = make_float2(acc[mt][nt][0], acc[mt][nt][1]);
                *(float2*)p1 = make_float2(acc[mt][nt][2], acc[mt][nt][3]);
            }
        return;
    }

    const int region = bn >> 11;
    const int head   = (bn & 2047) >> 7;
    __nv_bfloat16* dh = (region == 0) ? g_qh : (region == 1) ? g_kh : g_vh;
    __nv_bfloat16* dl = (region == 0) ? g_ql : (region == 1) ? g_kl : g_vl;

    if (region == 2) {
#pragma unroll
        for (int mt = 0; mt < 4; mt++) {
#pragma unroll
            for (int rr = 0; rr < 2; rr++) {
                int grow = bm + lr0 + mt * 16 + rr * 8;
                int t = grow & (T_ - 1), b = grow >> 11;
                size_t dst = ((size_t)(b * H_ + head) * T_ + t) * D_ + lc0;
#pragma unroll
                for (int nt = 0; nt < 4; nt++) {
                    unsigned h, l;
                    split2(acc[mt][nt][2 * rr], acc[mt][nt][2 * rr + 1], h, l);
                    *(unsigned*)(dh + dst + nt * 8) = h;
                    *(unsigned*)(dl + dst + nt * 8) = l;
                }
            }
        }
        return;
    }

    float* sf = (float*)smem;
#pragma unroll
    for (int mt = 0; mt < 4; mt++)
#pragma unroll
        for (int nt = 0; nt < 4; nt++) {
            int r0l = lr0 + mt * 16;
            *(float2*)&sf[(r0l)     * 132 + lc0 + nt * 8] = make_float2(acc[mt][nt][0], acc[mt][nt][1]);
            *(float2*)&sf[(r0l + 8) * 132 + lc0 + nt * 8] = make_float2(acc[mt][nt][2], acc[mt][nt][3]);
        }
    __syncthreads();

    const float qs = (region == 0) ? 0.088388347648318447f : 1.0f;
#pragma unroll 4
    for (int p = 0; p < 32; p++) {
        int linear = p * 256 + tid;
        int r = linear >> 6;
        int j = linear & 63;
        float s1 = sf[r * 132 + j];
        float s2 = sf[r * 132 + j + 64];
        int grow = bm + r;
        int t = grow & (T_ - 1), b = grow >> 11;
        float sn = g_sin[t * HALF_ + j];
        float cs = g_cos[t * HALF_ + j];
        float va = (s1 * cs - s2 * sn) * qs;
        float vb = (s2 * cs + s1 * sn) * qs;
        size_t dst = ((size_t)(b * H_ + head) * T_ + t) * D_ + j;
        splitw(va, dh, dl, dst);
        splitw(vb, dh, dl, dst + 64);
    }
}

// =================================================================================
//  Tensor-core causal flash attention:
//  exp + bf16 packing fused INTO the PV MMA stream (per 16-key group), so the
//  FFMA softmax work interleaves with HMMA issue instead of serializing.
// =================================================================================
#define FKH 0
#define FKL 16384
#define FVH 32768
#define FVL 49152
#define FSTAGE 65536
#define FSM_TOTAL 131072

__device__ __forceinline__ uint32_t fsw(int r, int c) {
    return (uint32_t)(r * 256 + ((((c ^ r) & 7) | (c & 8)) << 4));
}

__global__ void __launch_bounds__(256, 1) flash_mma_kernel()
{
    extern __shared__ char fsm[];
    const uint32_t sb = (uint32_t)__cvta_generic_to_shared(fsm);

    const int i0  = (gridDim.x - 1) - blockIdx.x;
    const int bh  = blockIdx.y;
    const int tid = threadIdx.x;
    const int lane = tid & 31;
    const int w    = tid >> 5;
    const int quad = lane >> 3;
    const int rq   = lane & 7;
    const int lr   = lane >> 2;
    const int lq   = lane & 3;

    const size_t kvbase   = (size_t)bh * (T_ * D_);
    const size_t qrowbase = kvbase + (size_t)i0 * 128 * D_;

    {
        int r  = tid >> 1;
        int cb = (tid & 1) * 8;
        const size_t g = qrowbase + (size_t)r * D_;
#pragma unroll
        for (int j = 0; j < 8; j++) {
            int c = cb + j;
            uint32_t sw = fsw(r, c);
            *(uint4*)(fsm + sw)         = *(const uint4*)(g_qh + g + c * 8);
            *(uint4*)(fsm + 32768 + sw) = *(const uint4*)(g_ql + g + c * 8);
        }
    }
    __syncthreads();

    const int kvr  = tid >> 2;
    const int kvcb = (tid & 3) * 4;
    const int jmax = 2 * i0 + 1;
#define KV_ISSUE(J, BUF) do { \
    const size_t g_ = kvbase + (size_t)((J) * 64 + kvr) * D_; \
    const uint32_t base_ = sb + (BUF) * FSTAGE; \
    _Pragma("unroll") for (int j_ = 0; j_ < 4; j_++) { \
        int c_ = kvcb + j_; \
        uint32_t sw_ = fsw(kvr, c_); \
        CP16(base_ + FKH + sw_, g_kh + g_ + c_ * 8); \
        CP16(base_ + FKL + sw_, g_kl + g_ + c_ * 8); \
        CP16(base_ + FVH + sw_, g_vh + g_ + c_ * 8); \
        CP16(base_ + FVL + sw_, g_vl + g_ + c_ * 8); } \
    CP_COMMIT(); } while (0)

    KV_ISSUE(0, 1);

    const int arow  = 16 * w + (quad & 1) * 8 + rq;
    const int rB    = (quad & 1) * 8 + rq;
    const int cHalf = quad >> 1;

    unsigned qh[8][4], ql[8][4];
#pragma unroll
    for (int kk = 0; kk < 8; kk++) {
        uint32_t aaddr = sb + fsw(arow, 2 * kk + cHalf);
        LDSM_X4(qh[kk][0], qh[kk][1], qh[kk][2], qh[kk][3], aaddr);
        LDSM_X4(ql[kk][0], ql[kk][1], ql[kk][2], ql[kk][3], aaddr + 32768);
    }

    float o[16][4];
#pragma unroll
    for (int dt = 0; dt < 16; dt++)
#pragma unroll
        for (int e = 0; e < 4; e++) o[dt][e] = 0.f;
    float mcur[2] = {-3.4e38f, -3.4e38f};
    float lcur[2] = {0.f, 0.f};

    int buf = 1;
    for (int j0 = 0; j0 <= jmax; j0++) {
        CP_WAIT0();
        __syncthreads();
        if (j0 < jmax) KV_ISSUE(j0 + 1, buf ^ 1);

        const uint32_t kvb = sb + buf * FSTAGE;

        // ---- S = Q K^T ----
        float s[8][4];
#pragma unroll
        for (int nt = 0; nt < 8; nt++)
#pragma unroll
            for (int e = 0; e < 4; e++) s[nt][e] = 0.f;

#pragma unroll
        for (int kk = 0; kk < 8; kk++) {
            const int ca = 2 * kk + cHalf;
            unsigned kh4[4][4], kl4[4][4];
#pragma unroll
            for (int p = 0; p < 4; p++) {
                uint32_t kaddr = kvb + fsw(16 * p + rB, ca);
                LDSM_X4(kh4[p][0], kh4[p][1], kh4[p][2], kh4[p][3], kaddr + FKH);
                LDSM_X4(kl4[p][0], kl4[p][1], kl4[p][2], kl4[p][3], kaddr + FKL);
            }
#pragma unroll
            for (int p = 0; p < 4; p++) {
                unsigned bh0[2] = {kh4[p][0], kh4[p][2]};
                unsigned bh1[2] = {kh4[p][1], kh4[p][3]};
                unsigned bl0[2] = {kl4[p][0], kl4[p][2]};
                unsigned bl1[2] = {kl4[p][1], kl4[p][3]};
                mma16816(s[2*p],   qh[kk], bh0);
                mma16816(s[2*p],   ql[kk], bh0);
                mma16816(s[2*p],   qh[kk], bl0);
                mma16816(s[2*p+1], qh[kk], bh1);
                mma16816(s[2*p+1], ql[kk], bh1);
                mma16816(s[2*p+1], qh[kk], bl1);
            }
        }

        // ---- causal mask ----
        if (j0 >= 2 * i0) {
            const int qr0 = i0 * 128 + 16 * w + lr;
            const int kc0 = j0 * 64 + 2 * lq;
#pragma unroll
            for (int nt = 0; nt < 8; nt++)
#pragma unroll
                for (int e = 0; e < 4; e++) {
                    int r = qr0 + (e >> 1) * 8;
                    int c = kc0 + 8 * nt + (e & 1);
                    if (c > r) s[nt][e] = -3.4e38f;
                }
        }

        // ---- max reduce + alpha + o-rescale (serial part, minimized) ----
        float mn[2], alpha[2];
#pragma unroll
        for (int z = 0; z < 2; z++) {
            float mx = -3.4e38f;
#pragma unroll
            for (int nt = 0; nt < 8; nt++)
                mx = fmaxf(mx, fmaxf(s[nt][2*z], s[nt][2*z+1]));
            mx = fmaxf(mx, __shfl_xor_sync(0xffffffffu, mx, 1));
            mx = fmaxf(mx, __shfl_xor_sync(0xffffffffu, mx, 2));
            mn[z]    = fmaxf(mcur[z], mx);
            alpha[z] = fast_exp(mcur[z] - mn[z]);
            mcur[z]  = mn[z];
#pragma unroll
            for (int dt = 0; dt < 16; dt++) {
                o[dt][2*z]   *= alpha[z];
                o[dt][2*z+1] *= alpha[z];
            }
        }

        // ---- fused exp + pack + PV per 16-key group (FFMA hides under HMMA) ----
        float ls0 = 0.f, ls1 = 0.f;
#pragma unroll
        for (int kk2 = 0; kk2 < 4; kk2++) {
            float e00 = fast_exp(s[2*kk2][0]   - mn[0]);
            float e01 = fast_exp(s[2*kk2][1]   - mn[0]);
            float e02 = fast_exp(s[2*kk2][2]   - mn[1]);
            float e03 = fast_exp(s[2*kk2][3]   - mn[1]);
            float e10 = fast_exp(s[2*kk2+1][0] - mn[0]);
            float e11 = fast_exp(s[2*kk2+1][1] - mn[0]);
            float e12 = fast_exp(s[2*kk2+1][2] - mn[1]);
            float e13 = fast_exp(s[2*kk2+1][3] - mn[1]);
            ls0 += e00 + e01 + e10 + e11;
            ls1 += e02 + e03 + e12 + e13;

            unsigned ph[4], pl[4];
            split2(e00, e01, ph[0], pl[0]);
            split2(e02, e03, ph[1], pl[1]);
            split2(e10, e11, ph[2], pl[2]);
            split2(e12, e13, ph[3], pl[3]);

            const int rV = 16 * kk2 + rB;
#pragma unroll
            for (int p = 0; p < 8; p++) {
                unsigned vh4[4], vl4[4];
                uint32_t vaddr = kvb + fsw(rV, 2 * p + cHalf);
                LDSM_X4_T(vh4[0], vh4[1], vh4[2], vh4[3], vaddr + FVH);
                LDSM_X4_T(vl4[0], vl4[1], vl4[2], vl4[3], vaddr + FVL);
                mma16816(o[2*p],   ph, &vh4[0]);
                mma16816(o[2*p],   pl, &vh4[0]);
                mma16816(o[2*p],   ph, &vl4[0]);
                mma16816(o[2*p+1], ph, &vh4[2]);
                mma16816(o[2*p+1], pl, &vh4[2]);
                mma16816(o[2*p+1], ph, &vl4[2]);
            }
        }

        // ---- finish l update ----
        ls0 += __shfl_xor_sync(0xffffffffu, ls0, 1);
        ls0 += __shfl_xor_sync(0xffffffffu, ls0, 2);
        ls1 += __shfl_xor_sync(0xffffffffu, ls1, 1);
        ls1 += __shfl_xor_sync(0xffffffffu, ls1, 2);
        lcur[0] = lcur[0] * alpha[0] + ls0;
        lcur[1] = lcur[1] * alpha[1] + ls1;

        buf ^= 1;
    }
#undef KV_ISSUE

    const float inv0 = 1.f / lcur[0];
    const float inv1 = 1.f / lcur[1];
    const size_t obase = ((size_t)bh * T_ + (size_t)i0 * 128 + 16 * w + lr) * D_;
#pragma unroll
    for (int dt = 0; dt < 16; dt++) {
        int col = 8 * dt + 2 * lq;
        unsigned h0, l0, h1, l1;
        split2(o[dt][0] * inv0, o[dt][1] * inv0, h0, l0);
        split2(o[dt][2] * inv1, o[dt][3] * inv1, h1, l1);
        *(unsigned*)(g_oh + obase + col)          = h0;
        *(unsigned*)(g_ol + obase + col)          = l0;
        *(unsigned*)(g_oh + obase + 8 * D_ + col) = h1;
        *(unsigned*)(g_ol + obase + 8 * D_ + col) = l1;
    }
}

// ---------------- launch ----------------
extern "C" void kernel_launch(void* const* d_in, const int* in_sizes, int n_in,
                              void* d_out, int out_size)
{
    const float* x    = (const float*)d_in[0];
    const float* Wqkv = (const float*)d_in[1];
    const float* Wout = (const float*)d_in[2];
    float* out = (float*)d_out;

    __nv_bfloat16 *xh, *xl, *w1h, *w1l, *w2h, *w2l, *oh, *ol;
    cudaGetSymbolAddress((void**)&xh,  g_xh);
    cudaGetSymbolAddress((void**)&xl,  g_xl);
    cudaGetSymbolAddress((void**)&w1h, g_w1h);
    cudaGetSymbolAddress((void**)&w1l, g_w1l);
    cudaGetSymbolAddress((void**)&w2h, g_w2h);
    cudaGetSymbolAddress((void**)&w2l, g_w2l);
    cudaGetSymbolAddress((void**)&oh,  g_oh);
    cudaGetSymbolAddress((void**)&ol,  g_ol);

    cudaFuncSetAttribute(mma_gemm, cudaFuncAttributeMaxDynamicSharedMemorySize, GSM_TOTAL);
    cudaFuncSetAttribute(flash_mma_kernel, cudaFuncAttributeMaxDynamicSharedMemorySize, FSM_TOTAL);

    // 0) merged prep
    prep_kernel<<<(unsigned)PB_TOTAL, 256>>>(x, Wqkv, Wout);
    // 1) QKV projection with fused rope/scale/split/transpose epilogue
    mma_gemm<<<dim3(N1_ / 128, M_ / 128), 256, GSM_TOTAL>>>(xh, xl, w1h, w1l, nullptr, M_, N1_, C_, 1);
    // 2) tensor-core causal flash attention (fused softmax/PV)
    flash_mma_kernel<<<dim3(T_ / 128, BH_), 256, FSM_TOTAL>>>();
    // 3) output projection
    mma_gemm<<<dim3(C_ / 128, M_ / 128), 256, GSM_TOTAL>>>(oh, ol, w2h, w2l, out, M_, C_, C_, 0);
}